// round 9
// baseline (speedup 1.0000x reference)
#include <cuda_runtime.h>
#include <math.h>
#include <stdint.h>

// ---------------------------------------------------------------------------
// Problem constants
// ---------------------------------------------------------------------------
#define T_STEPS 256
#define BATCH   16
#define HID     4096          // H
#define PROJ    512           // P
#define G4H     16384         // 4*H
#define F1      532
#define F2CON   768           // con_x features (1280-512)
#define NBLK    128           // persistent grid size
#define HSTR    20            // padded smem row stride (floats) for h tiles

// persistent-kernel smem layout (floats)
#define SM_RED_OFF_F  20480
#define SM_Z_OFF_F    34816
#define SM_TOTAL_B    147456

// sgemm dynamic smem: AsD 2*16*130 ull (33280 B) + Bs 2*16*132 f (16896 B)
#define SG_ASD_ULL   (2 * 16 * 130)
#define SG_BS_OFF_F  (SG_ASD_ULL * 2)          // in floats
#define SG_SMEM_B    (SG_ASD_ULL * 8 + 2 * 16 * 132 * 4)   // 50176

// ---------------------------------------------------------------------------
// Device scratch (static only — no cudaMalloc allowed)
// ---------------------------------------------------------------------------
__device__ float g_xg1[(size_t)T_STEPS * BATCH * G4H];   // 268 MB
__device__ float g_xg2[(size_t)T_STEPS * BATCH * G4H];   // 268 MB
__device__ float g_Wt1[(size_t)512 * G4H];               // W_hh1^T  [k][row]
__device__ float g_Wt2[(size_t)1024 * G4H];              // [W_ih2[:,:512]; W_hh2]^T
__device__ float g_Wtr1[(size_t)HID * PROJ];             // W_hr1^T [k][p]
__device__ float g_Wtr2[(size_t)HID * PROJ];
__device__ float g_out1[(size_t)(T_STEPS + 1) * BATCH * PROJ];
__device__ float g_out2[(size_t)(T_STEPS + 1) * BATCH * PROJ];
__device__ float g_c1[BATCH * HID];
__device__ float g_c2[BATCH * HID];
__device__ float g_g1h[BATCH * HID];
__device__ float g_g2h[BATCH * HID];
__device__ int   g_counts[T_STEPS];
__device__ int   g_offsets[T_STEPS + 1];

__device__ volatile unsigned g_genv;   // monotonic across replays
__device__ unsigned g_arrive;          // self-resetting

// ---------------------------------------------------------------------------
// packed f32x2 helpers
// ---------------------------------------------------------------------------
__device__ __forceinline__ unsigned long long pk2(float x, float y) {
    unsigned long long d;
    asm("mov.b64 %0, {%1, %2};" : "=l"(d) : "f"(x), "f"(y));
    return d;
}
__device__ __forceinline__ void fma2(unsigned long long& a, unsigned long long b,
                                     unsigned long long c) {
    asm("fma.rn.f32x2 %0, %1, %2, %0;" : "+l"(a) : "l"(b), "l"(c));
}
__device__ __forceinline__ unsigned long long add2(unsigned long long a,
                                                   unsigned long long b) {
    unsigned long long d;
    asm("add.rn.f32x2 %0, %1, %2;" : "=l"(d) : "l"(a), "l"(b));
    return d;
}
__device__ __forceinline__ float2 up2(unsigned long long d) {
    float2 r;
    asm("mov.b64 {%0, %1}, %2;" : "=f"(r.x), "=f"(r.y) : "l"(d));
    return r;
}
__device__ __forceinline__ float sigf(float x) { return 1.f / (1.f + expf(-x)); }

// ---------------------------------------------------------------------------
// grid-wide barrier (release/acquire via threadfence + gen counter)
// ---------------------------------------------------------------------------
__device__ __forceinline__ void gsync(unsigned& gen) {
    __syncthreads();
    if (threadIdx.x == 0) {
        unsigned next = gen + 1;
        __threadfence();
        if (atomicAdd(&g_arrive, 1u) == (unsigned)(NBLK - 1)) {
            g_arrive = 0u;
            __threadfence();
            g_genv = next;
        } else {
            while (g_genv != next) {}
            __threadfence();
        }
        gen = next;
    }
    __syncthreads();
}

// ---------------------------------------------------------------------------
// init
// ---------------------------------------------------------------------------
__global__ void zero_kernel() {
    const size_t n1 = (size_t)(T_STEPS + 1) * BATCH * PROJ;
    const size_t nc = (size_t)BATCH * HID;
    const size_t tot = 2 * n1 + 2 * nc;
    for (size_t i = (size_t)blockIdx.x * blockDim.x + threadIdx.x; i < tot;
         i += (size_t)gridDim.x * blockDim.x) {
        if (i < n1)               g_out1[i] = 0.f;
        else if (i < 2 * n1)      g_out2[i - n1] = 0.f;
        else if (i < 2 * n1 + nc) g_c1[i - 2 * n1] = 0.f;
        else                      g_c2[i - 2 * n1 - nc] = 0.f;
    }
}

// ---------------------------------------------------------------------------
// Fused transpose of all 5 weight matrices in ONE launch.
// ---------------------------------------------------------------------------
__global__ void transpose_all(const float* __restrict__ W_hh1,
                              const float* __restrict__ W_ih2,
                              const float* __restrict__ W_hh2,
                              const float* __restrict__ W_hr1,
                              const float* __restrict__ W_hr2) {
    __shared__ float tile[32][33];
    int bid = blockIdx.x;
    const float* in;
    float* out;
    int rows, ldin, tix;
    if (bid < 8192)       { in = W_hh1; out = g_Wt1;  rows = G4H; ldin = 512;  tix = bid; }
    else if (bid < 16384) { in = W_ih2; out = g_Wt2;  rows = G4H; ldin = 1280; tix = bid - 8192; }
    else if (bid < 24576) { in = W_hh2; out = g_Wt2 + (size_t)512 * G4H;
                                                       rows = G4H; ldin = 512;  tix = bid - 16384; }
    else if (bid < 26624) { in = W_hr1; out = g_Wtr1; rows = 512; ldin = HID;  tix = bid - 24576; }
    else                  { in = W_hr2; out = g_Wtr2; rows = 512; ldin = HID;  tix = bid - 26624; }

    int nbx = rows >> 5;
    int bx = tix % nbx, by = tix / nbx;
    int j0 = bx * 32, k0 = by * 32;
    int tx = threadIdx.x, ty = threadIdx.y;
    #pragma unroll
    for (int i = 0; i < 32; i += 8) {
        int j = j0 + ty + i, k = k0 + tx;
        tile[ty + i][tx] = in[(size_t)j * ldin + k];
    }
    __syncthreads();
    #pragma unroll
    for (int i = 0; i < 32; i += 8) {
        int k = k0 + ty + i, j = j0 + tx;
        out[(size_t)k * rows + j] = tile[tx][ty + i];
    }
}

// ---------------------------------------------------------------------------
// SGEMM (NT): double-buffered smem (ONE sync/tile), unchecked main tiles,
// streaming C stores. C[m][n] = A[m]·B[n] + bias[n]
// ---------------------------------------------------------------------------
__global__ void __launch_bounds__(256, 2)
sgemm_nt(const float* __restrict__ A, const float* __restrict__ B,
         const float* __restrict__ bias, float* __restrict__ C,
         int K, int lda, int ldb, int boff) {
    extern __shared__ float sgsm[];
    unsigned long long* AsD = (unsigned long long*)sgsm;       // [2][16][130]
    float* Bs = sgsm + SG_BS_OFF_F;                             // [2][16][132]

    const int tid = threadIdx.x;
    const int tx = tid & 15, ty = tid >> 4;
    const int m0 = blockIdx.y * 128, n0 = blockIdx.x * 128;

    unsigned long long acc[8][4];
    #pragma unroll
    for (int i = 0; i < 8; i++)
        #pragma unroll
        for (int j = 0; j < 4; j++) acc[i][j] = 0ull;

    const int rr = tid >> 4;      // 0..15
    const int cc = tid & 15;      // 0..15

    float ar[8], br[8];
    // prefetch tile 0 (K >= 16 always, unchecked)
    #pragma unroll
    for (int i = 0; i < 8; i++) {
        int r = rr + i * 16;
        ar[i] = A[(size_t)(m0 + r) * lda + cc];
        br[i] = B[(size_t)(n0 + r) * ldb + boff + cc];
    }
    // commit tile 0 -> buf 0
    #pragma unroll
    for (int i = 0; i < 8; i++) {
        int r = rr + i * 16;
        AsD[cc * 130 + r] = pk2(ar[i], ar[i]);
        Bs[cc * 132 + r]  = br[i];
    }
    __syncthreads();

    int cur = 0;
    for (int k0 = 0; k0 < K; k0 += 16) {
        const int kn = k0 + 16;
        const bool haveNext = kn < K;
        if (kn + 16 <= K) {                    // full next tile: unchecked
            #pragma unroll
            for (int i = 0; i < 8; i++) {
                int r = rr + i * 16;
                ar[i] = A[(size_t)(m0 + r) * lda + kn + cc];
                br[i] = B[(size_t)(n0 + r) * ldb + boff + kn + cc];
            }
        } else if (haveNext) {                 // partial tail: checked
            #pragma unroll
            for (int i = 0; i < 8; i++) {
                int r = rr + i * 16;
                ar[i] = (kn + cc < K) ? A[(size_t)(m0 + r) * lda + kn + cc] : 0.f;
                br[i] = (kn + cc < K) ? B[(size_t)(n0 + r) * ldb + boff + kn + cc] : 0.f;
            }
        }
        const unsigned long long* asd = AsD + cur * (16 * 130);
        const float* bsp = Bs + cur * (16 * 132);
        #pragma unroll
        for (int kk = 0; kk < 16; kk++) {
            unsigned long long ad[8];
            *(ulonglong2*)&ad[0] = *(const ulonglong2*)&asd[kk * 130 + ty * 8];
            *(ulonglong2*)&ad[2] = *(const ulonglong2*)&asd[kk * 130 + ty * 8 + 2];
            *(ulonglong2*)&ad[4] = *(const ulonglong2*)&asd[kk * 130 + ty * 8 + 4];
            *(ulonglong2*)&ad[6] = *(const ulonglong2*)&asd[kk * 130 + ty * 8 + 6];
            ulonglong2 bq0 = *(const ulonglong2*)&bsp[kk * 132 + tx * 8];
            ulonglong2 bq1 = *(const ulonglong2*)&bsp[kk * 132 + tx * 8 + 4];
            #pragma unroll
            for (int i = 0; i < 8; i++) {
                fma2(acc[i][0], ad[i], bq0.x);
                fma2(acc[i][1], ad[i], bq0.y);
                fma2(acc[i][2], ad[i], bq1.x);
                fma2(acc[i][3], ad[i], bq1.y);
            }
        }
        if (haveNext) {
            unsigned long long* asn = AsD + (cur ^ 1) * (16 * 130);
            float* bsn = Bs + (cur ^ 1) * (16 * 132);
            #pragma unroll
            for (int i = 0; i < 8; i++) {
                int r = rr + i * 16;
                asn[cc * 130 + r] = pk2(ar[i], ar[i]);
                bsn[cc * 132 + r] = br[i];
            }
            __syncthreads();
            cur ^= 1;
        }
    }

    float bv[8];
    #pragma unroll
    for (int j = 0; j < 8; j++) bv[j] = bias[n0 + tx * 8 + j];
    #pragma unroll
    for (int i = 0; i < 8; i++) {
        size_t rowoff = (size_t)(m0 + ty * 8 + i) * G4H + n0 + tx * 8;
        float2 v0 = up2(acc[i][0]), v1 = up2(acc[i][1]);
        float2 v2 = up2(acc[i][2]), v3 = up2(acc[i][3]);
        float4 o0 = {v0.x + bv[0], v0.y + bv[1], v1.x + bv[2], v1.y + bv[3]};
        float4 o1 = {v2.x + bv[4], v2.y + bv[5], v3.x + bv[6], v3.y + bv[7]};
        __stcs((float4*)(C + rowoff), o0);        // streaming: don't thrash L2
        __stcs((float4*)(C + rowoff + 4), o1);
    }
}

// ---------------------------------------------------------------------------
// Stage h into hsf[k*HSTR + b]. KROWS rows; src1 covers k<512, src2 the rest.
// ---------------------------------------------------------------------------
template <int KROWS>
__device__ __forceinline__ void stage_h(const float* __restrict__ src1,
                                        const float* __restrict__ src2,
                                        float* hsf) {
    const int tid = threadIdx.x;
    for (int idx = tid; idx < 4 * KROWS; idx += 512) {
        int bb, k;
        if (KROWS == 512) { bb = idx >> 9;  k = idx & 511;  }
        else              { bb = idx >> 10; k = idx & 1023; }
        int b0 = 4 * bb;
        const float* s = (KROWS == 512 || k < 512) ? (src1 + k) : (src2 + (k - 512));
        float4 v;
        v.x = s[(b0 + 0) * PROJ];
        v.y = s[(b0 + 1) * PROJ];
        v.z = s[(b0 + 2) * PROJ];
        v.w = s[(b0 + 3) * PROJ];
        *(float4*)&hsf[k * HSTR + 4 * bb] = v;
    }
}

// ---------------------------------------------------------------------------
// Gate core: 512 threads, 8-way K split, micro-tile 8 rows x 4 batches.
// xg read via __ldcs (single-use stream, evict-first keeps weights in L2).
// ---------------------------------------------------------------------------
template <int KTOT>
__device__ __forceinline__ void gate_core(
    const float* __restrict__ Wt, const float* __restrict__ xg,
    float& cref, float* __restrict__ gh, float* __restrict__ cglob, bool last,
    const float* hsf, ulonglong2* redu2, float* zbuf)
{
    const int tid = threadIdx.x;
    const int ksub = tid >> 6;            // 0..7
    const int r    = tid & 63;            // 0..63
    const int rowg = r >> 2;              // 0..15
    const int bg   = (r & 3) << 2;        // 0,4,8,12
    const int gate = rowg >> 2;           // 0..3
    const int j0   = blockIdx.x * 32;
    const int jj   = (rowg & 3) << 3;     // 0,8,16,24
    const int row8 = gate * HID + j0 + jj;
    const int kh   = KTOT / 8;
    const int kbeg = ksub * kh;

    const ulonglong2* wp = (const ulonglong2*)(Wt + (size_t)kbeg * G4H + row8);
    const float* hp = hsf + (size_t)kbeg * HSTR + bg;

    unsigned long long acc[4][4];
    #pragma unroll
    for (int i = 0; i < 4; i++)
        #pragma unroll
        for (int j = 0; j < 4; j++) acc[i][j] = 0ull;

    #pragma unroll 8
    for (int k = 0; k < kh; k++) {
        ulonglong2 wa = wp[(size_t)k * (G4H / 4)];
        ulonglong2 wb = wp[(size_t)k * (G4H / 4) + 1];
        float4 h = *(const float4*)(hp + k * HSTR);
        unsigned long long h0 = pk2(h.x, h.x), h1 = pk2(h.y, h.y);
        unsigned long long h2 = pk2(h.z, h.z), h3 = pk2(h.w, h.w);
        fma2(acc[0][0], wa.x, h0); fma2(acc[0][1], wa.x, h1);
        fma2(acc[0][2], wa.x, h2); fma2(acc[0][3], wa.x, h3);
        fma2(acc[1][0], wa.y, h0); fma2(acc[1][1], wa.y, h1);
        fma2(acc[1][2], wa.y, h2); fma2(acc[1][3], wa.y, h3);
        fma2(acc[2][0], wb.x, h0); fma2(acc[2][1], wb.x, h1);
        fma2(acc[2][2], wb.x, h2); fma2(acc[2][3], wb.x, h3);
        fma2(acc[3][0], wb.y, h0); fma2(acc[3][1], wb.y, h1);
        fma2(acc[3][2], wb.y, h2); fma2(acc[3][3], wb.y, h3);
    }

    if (ksub > 0) {
        ulonglong2* dst = redu2 + (size_t)(ksub - 1) * 512 + r;
        #pragma unroll
        for (int rp = 0; rp < 4; rp++)
            #pragma unroll
            for (int bh = 0; bh < 2; bh++)
                dst[(rp * 2 + bh) * 64] = make_ulonglong2(acc[rp][2 * bh],
                                                          acc[rp][2 * bh + 1]);
    }
    __syncthreads();

    if (ksub == 0) {
        #pragma unroll
        for (int g = 0; g < 7; g++) {
            const ulonglong2* src = redu2 + (size_t)g * 512 + r;
            #pragma unroll
            for (int rp = 0; rp < 4; rp++)
                #pragma unroll
                for (int bh = 0; bh < 2; bh++) {
                    ulonglong2 v = src[(rp * 2 + bh) * 64];
                    acc[rp][2 * bh]     = add2(acc[rp][2 * bh], v.x);
                    acc[rp][2 * bh + 1] = add2(acc[rp][2 * bh + 1], v.y);
                }
        }
        #pragma unroll
        for (int bi = 0; bi < 4; bi++) {
            const float* xr = xg + (size_t)(bg + bi) * G4H + row8;
            float4 x0 = __ldcs((const float4*)xr);
            float4 x1 = __ldcs((const float4*)(xr + 4));
            float2 a0 = up2(acc[0][bi]), a1 = up2(acc[1][bi]);
            float2 a2 = up2(acc[2][bi]), a3 = up2(acc[3][bi]);
            float4 z0 = {a0.x + x0.x, a0.y + x0.y, a1.x + x0.z, a1.y + x0.w};
            float4 z1 = {a2.x + x1.x, a2.y + x1.y, a3.x + x1.z, a3.y + x1.w};
            float* zb = &zbuf[gate * 512 + (bg + bi) * 32 + jj];
            *(float4*)zb = z0;
            *(float4*)(zb + 4) = z1;
        }
    }
    __syncthreads();

    {
        int b = tid >> 5, jl = tid & 31;
        float zi = zbuf[0 * 512 + b * 32 + jl];
        float zf = zbuf[1 * 512 + b * 32 + jl];
        float zg = zbuf[2 * 512 + b * 32 + jl];
        float zo = zbuf[3 * 512 + b * 32 + jl];
        size_t off = (size_t)b * HID + j0 + jl;
        float cn = sigf(zf) * cref + sigf(zi) * tanhf(zg);
        cref = cn;
        gh[off] = sigf(zo) * tanhf(cn);
        if (last) cglob[off] = cn;
    }
}

// ---------------------------------------------------------------------------
// Proj staging + core.
// ---------------------------------------------------------------------------
__device__ __forceinline__ void stage_g(const float* __restrict__ gh,
                                        int kb, float* gpf) {
    const int tid = threadIdx.x;
    int bb = tid >> 7, k = tid & 127;
    int b0 = 4 * bb;
    float4 v;
    v.x = __ldcs(gh + (size_t)(b0 + 0) * HID + kb + k);
    v.y = __ldcs(gh + (size_t)(b0 + 1) * HID + kb + k);
    v.z = __ldcs(gh + (size_t)(b0 + 2) * HID + kb + k);
    v.w = __ldcs(gh + (size_t)(b0 + 3) * HID + kb + k);
    *(float4*)&gpf[k * HSTR + 4 * bb] = v;
}

__device__ __forceinline__ void proj_core(
    const float* gpf, const float* __restrict__ Wtr,
    float* __restrict__ hout, int p0, int kb, unsigned long long* predu)
{
    const int tid = threadIdx.x;
    const int ks = tid >> 7, r = tid & 127;
    const int rowg = r >> 2, bg = (r & 3) << 2;
    const int p4 = p0 + rowg * 4;
    const int kbeg = ks * 32;

    const ulonglong2* wp = (const ulonglong2*)(Wtr + (size_t)(kb + kbeg) * PROJ + p4);
    const float* hp = gpf + kbeg * HSTR + bg;

    unsigned long long acc[2][4];
    #pragma unroll
    for (int i = 0; i < 2; i++)
        #pragma unroll
        for (int j = 0; j < 4; j++) acc[i][j] = 0ull;

    #pragma unroll 8
    for (int k = 0; k < 32; k++) {
        ulonglong2 w = wp[(size_t)k * (PROJ / 4)];
        float4 h = *(const float4*)(hp + k * HSTR);
        unsigned long long h0 = pk2(h.x, h.x), h1 = pk2(h.y, h.y);
        unsigned long long h2 = pk2(h.z, h.z), h3 = pk2(h.w, h.w);
        fma2(acc[0][0], w.x, h0); fma2(acc[1][0], w.y, h0);
        fma2(acc[0][1], w.x, h1); fma2(acc[1][1], w.y, h1);
        fma2(acc[0][2], w.x, h2); fma2(acc[1][2], w.y, h2);
        fma2(acc[0][3], w.x, h3); fma2(acc[1][3], w.y, h3);
    }

    if (ks > 0) {
        unsigned long long* dst = predu + (size_t)(ks - 1) * 1152 + r * 9;
        #pragma unroll
        for (int rp = 0; rp < 2; rp++)
            #pragma unroll
            for (int bi = 0; bi < 4; bi++) dst[rp * 4 + bi] = acc[rp][bi];
    }
    __syncthreads();

    if (ks == 0) {
        #pragma unroll
        for (int g = 0; g < 3; g++) {
            const unsigned long long* src = predu + (size_t)g * 1152 + r * 9;
            #pragma unroll
            for (int rp = 0; rp < 2; rp++)
                #pragma unroll
                for (int bi = 0; bi < 4; bi++)
                    acc[rp][bi] = add2(acc[rp][bi], src[rp * 4 + bi]);
        }
        #pragma unroll
        for (int bi = 0; bi < 4; bi++) {
            float2 a0 = up2(acc[0][bi]);
            float2 a1 = up2(acc[1][bi]);
            float* o = hout + (size_t)(bg + bi) * PROJ + p4;
            atomicAdd(o + 0, a0.x);
            atomicAdd(o + 1, a0.y);
            atomicAdd(o + 2, a1.x);
            atomicAdd(o + 3, a1.y);
        }
    }
}

// ---------------------------------------------------------------------------
// Persistent recurrence with layer pipelining:
//   prologue: G1(0), P1(0)
//   loop t=0..254:  [G1(t+1) ; G2(t)]  |barrier|  [P1(t+1) ; P2(t)]  |barrier|
//   tail: G2(255), P2(255)
// ---------------------------------------------------------------------------
__global__ void __launch_bounds__(512, 1) recurrence_kernel() {
    extern __shared__ float smem[];
    float* hsf  = smem;
    ulonglong2* redu2 = (ulonglong2*)(smem + SM_RED_OFF_F);
    float* zbuf = smem + SM_Z_OFF_F;
    float* gpf1 = smem;
    float* gpf2 = smem + 2560;
    unsigned long long* predu = (unsigned long long*)(smem + 5120);

    const int pt = blockIdx.x & 3;
    const int kc = blockIdx.x >> 2;
    const int p0 = pt * 128, kb = kc * 128;

    unsigned gen = g_genv;
    float c1r = 0.f, c2r = 0.f;

    // prologue: G1(0)
    stage_h<512>(g_out1, nullptr, hsf);
    __syncthreads();
    gate_core<512>(g_Wt1, g_xg1, c1r, g_g1h, g_c1, false, hsf, redu2, zbuf);
    gsync(gen);
    // P1(0) -> out1[1]
    stage_g(g_g1h, kb, gpf1);
    __syncthreads();
    proj_core(gpf1, g_Wtr1, g_out1 + (size_t)1 * (BATCH * PROJ), p0, kb, predu);
    gsync(gen);

    for (int t = 0; t < T_STEPS - 1; t++) {
        stage_h<1024>(g_out1 + (size_t)(t + 1) * (BATCH * PROJ),
                      g_out2 + (size_t)t * (BATCH * PROJ), hsf);
        __syncthreads();
        gate_core<512>(g_Wt1, g_xg1 + (size_t)(t + 1) * BATCH * G4H,
                       c1r, g_g1h, g_c1, (t + 1 == T_STEPS - 1),
                       hsf, redu2, zbuf);
        __syncthreads();
        gate_core<1024>(g_Wt2, g_xg2 + (size_t)t * BATCH * G4H,
                        c2r, g_g2h, g_c2, false, hsf, redu2, zbuf);
        gsync(gen);
        stage_g(g_g1h, kb, gpf1);
        stage_g(g_g2h, kb, gpf2);
        __syncthreads();
        proj_core(gpf1, g_Wtr1, g_out1 + (size_t)(t + 2) * (BATCH * PROJ),
                  p0, kb, predu);
        __syncthreads();
        proj_core(gpf2, g_Wtr2, g_out2 + (size_t)(t + 1) * (BATCH * PROJ),
                  p0, kb, predu);
        gsync(gen);
    }

    // tail: G2(255), P2(255)
    {
        int t = T_STEPS - 1;
        stage_h<1024>(g_out1 + (size_t)(t + 1) * (BATCH * PROJ),
                      g_out2 + (size_t)t * (BATCH * PROJ), hsf);
        __syncthreads();
        gate_core<1024>(g_Wt2, g_xg2 + (size_t)t * BATCH * G4H,
                        c2r, g_g2h, g_c2, true, hsf, redu2, zbuf);
        gsync(gen);
        stage_g(g_g2h, kb, gpf1);
        __syncthreads();
        proj_core(gpf1, g_Wtr2, g_out2 + (size_t)(t + 1) * (BATCH * PROJ),
                  p0, kb, predu);
    }
}

// ---------------------------------------------------------------------------
// Packed-sequence bookkeeping
// ---------------------------------------------------------------------------
__global__ void counts_kernel(const int* __restrict__ lens) {
    int t = threadIdx.x;
    int c = 0;
    #pragma unroll
    for (int b = 0; b < BATCH; b++) c += (lens[b] > t) ? 1 : 0;
    g_counts[t] = c;
    __syncthreads();
    if (t == 0) {
        int s = 0;
        for (int i = 0; i < T_STEPS; i++) { g_offsets[i] = s; s += g_counts[i]; }
        g_offsets[T_STEPS] = s;
    }
}

// ---------------------------------------------------------------------------
// Heads: one warp per packed token
// ---------------------------------------------------------------------------
__global__ void __launch_bounds__(512) heads_kernel(
    const float* __restrict__ Wp, const float* __restrict__ bp,
    const float* __restrict__ Wa, const float* __restrict__ ba,
    float* __restrict__ out, int total) {
    const int t = blockIdx.x;
    const int w = threadIdx.x >> 5;
    const int lane = threadIdx.x & 31;
    if (w >= g_counts[t]) return;
    const int b = w;
    const int tok = g_offsets[t] + b;

    const float* o1 = g_out1 + (size_t)(t + 1) * (BATCH * PROJ) + (size_t)b * PROJ;
    const float* o2 = g_out2 + (size_t)(t + 1) * (BATCH * PROJ) + (size_t)b * PROJ;
    float v[16];
    #pragma unroll
    for (int i = 0; i < 16; i++) v[i] = o1[lane + 32 * i] + o2[lane + 32 * i];

    __shared__ float sp[16][20];
    __shared__ float sa[16][20];
    #pragma unroll
    for (int o = 0; o < 20; o++) {
        float s1 = 0.f, s2 = 0.f;
        #pragma unroll
        for (int i = 0; i < 16; i++) {
            float x = v[i];
            s1 = fmaf(x, Wp[o * PROJ + lane + 32 * i], s1);
            s2 = fmaf(x, Wa[o * PROJ + lane + 32 * i], s2);
        }
        #pragma unroll
        for (int off = 16; off; off >>= 1) {
            s1 += __shfl_xor_sync(0xffffffffu, s1, off);
            s2 += __shfl_xor_sync(0xffffffffu, s2, off);
        }
        if (lane == 0) { sp[w][o] = s1 + bp[o]; sa[w][o] = s2 + ba[o]; }
    }
    __syncwarp();
    if (lane == 0) {
        float m = -1e30f;
        #pragma unroll
        for (int o = 0; o < 20; o++) m = fmaxf(m, sp[w][o]);
        float e[20], sum = 0.f;
        #pragma unroll
        for (int o = 0; o < 20; o++) { e[o] = expf(sp[w][o] - m); sum += e[o]; }
        float inv = 1.f / sum;
        float* aa = out + (size_t)total * 20;
        #pragma unroll
        for (int o = 0; o < 20; o++) {
            out[(size_t)tok * 20 + o] = e[o] * inv;
            aa[(size_t)tok * 20 + o]  = sa[w][o];
        }
    }
}

// ---------------------------------------------------------------------------
// Final states: h1, c1, h2, c2
// ---------------------------------------------------------------------------
__global__ void finalize_kernel(float* __restrict__ out, int total) {
    const size_t base = (size_t)total * 40;
    const int nH = BATCH * PROJ;
    const int nC = BATCH * HID;
    int idx = blockIdx.x * blockDim.x + threadIdx.x;
    if (idx >= 2 * (nH + nC)) return;
    float v;
    if (idx < nH)                v = g_out1[(size_t)T_STEPS * nH + idx];
    else if (idx < nH + nC)      v = g_c1[idx - nH];
    else if (idx < 2 * nH + nC)  v = g_out2[(size_t)T_STEPS * nH + (idx - nH - nC)];
    else                         v = g_c2[idx - 2 * nH - nC];
    out[base + idx] = v;
}

// ---------------------------------------------------------------------------
// Host launch
// ---------------------------------------------------------------------------
extern "C" void kernel_launch(void* const* d_in, const int* in_sizes, int n_in,
                              void* d_out, int out_size) {
    const float* uncon  = (const float*)d_in[0];
    const float* con    = (const float*)d_in[1];
    const int*   lens   = (const int*)d_in[2];
    const float* W_ih1  = (const float*)d_in[3];
    const float* b1     = (const float*)d_in[4];
    const float* W_hh1  = (const float*)d_in[5];
    const float* W_hr1  = (const float*)d_in[6];
    const float* W_ih2  = (const float*)d_in[7];
    const float* b2     = (const float*)d_in[8];
    const float* W_hh2  = (const float*)d_in[9];
    const float* W_hr2  = (const float*)d_in[10];
    const float* W_pssm = (const float*)d_in[11];
    const float* b_pssm = (const float*)d_in[12];
    const float* W_aa   = (const float*)d_in[13];
    const float* b_aa   = (const float*)d_in[14];
    float* out = (float*)d_out;

    const int total = (out_size - 2 * (BATCH * PROJ + BATCH * HID)) / 40;

    float *p_xg1, *p_xg2;
    cudaGetSymbolAddress((void**)&p_xg1, g_xg1);
    cudaGetSymbolAddress((void**)&p_xg2, g_xg2);

    cudaFuncSetAttribute(recurrence_kernel,
                         cudaFuncAttributeMaxDynamicSharedMemorySize, SM_TOTAL_B);
    cudaFuncSetAttribute(sgemm_nt,
                         cudaFuncAttributeMaxDynamicSharedMemorySize, SG_SMEM_B);

    zero_kernel<<<2048, 256>>>();
    transpose_all<<<28672, dim3(32, 8)>>>(W_hh1, W_ih2, W_hh2, W_hr1, W_hr2);
    sgemm_nt<<<dim3(G4H / 128, (T_STEPS * BATCH) / 128), 256, SG_SMEM_B>>>(
        uncon, W_ih1, b1, p_xg1, F1, F1, F1, 0);
    sgemm_nt<<<dim3(G4H / 128, (T_STEPS * BATCH) / 128), 256, SG_SMEM_B>>>(
        con, W_ih2, b2, p_xg2, F2CON, F2CON, 1280, 512);
    counts_kernel<<<1, 256>>>(lens);
    recurrence_kernel<<<NBLK, 512, SM_TOTAL_B>>>();
    heads_kernel<<<T_STEPS, 512>>>(W_pssm, b_pssm, W_aa, b_aa, out, total);
    finalize_kernel<<<(2 * (BATCH * PROJ + BATCH * HID) + 255) / 256, 256>>>(out, total);
}

// round 10
// speedup vs baseline: 1.0355x; 1.0355x over previous
#include <cuda_runtime.h>
#include <math.h>
#include <stdint.h>

// ---------------------------------------------------------------------------
// Problem constants
// ---------------------------------------------------------------------------
#define T_STEPS 256
#define BATCH   16
#define HID     4096          // H
#define PROJ    512           // P
#define G4H     16384         // 4*H
#define F1      532
#define F2CON   768           // con_x features (1280-512)
#define NBLK    128           // persistent grid size
#define HSTR    20            // padded smem row stride (floats) for h tiles

// persistent-kernel smem layout (floats)
#define SM_RED_OFF_F  20480
#define SM_Z_OFF_F    34816
#define SM_TOTAL_B    147456

#define TSTR 136              // tf32 sgemm smem stride (floats)

// ---------------------------------------------------------------------------
// Device scratch (static only — no cudaMalloc allowed)
// ---------------------------------------------------------------------------
__device__ float g_xg1[(size_t)T_STEPS * BATCH * G4H];   // 268 MB
__device__ float g_xg2[(size_t)T_STEPS * BATCH * G4H];   // 268 MB
__device__ float g_Wt1[(size_t)512 * G4H];               // W_hh1^T  [k][row]
__device__ float g_Wt2[(size_t)1024 * G4H];              // [W_ih2[:,:512]; W_hh2]^T
__device__ float g_Wtr1[(size_t)HID * PROJ];             // W_hr1^T [k][p]
__device__ float g_Wtr2[(size_t)HID * PROJ];
__device__ float g_out1[(size_t)(T_STEPS + 1) * BATCH * PROJ];
__device__ float g_out2[(size_t)(T_STEPS + 1) * BATCH * PROJ];
__device__ float g_c1[BATCH * HID];
__device__ float g_c2[BATCH * HID];
__device__ float g_g1h[BATCH * HID];
__device__ float g_g2h[BATCH * HID];
__device__ int   g_counts[T_STEPS];
__device__ int   g_offsets[T_STEPS + 1];

__device__ volatile unsigned g_genv;   // monotonic across replays
__device__ unsigned g_arrive;          // self-resetting

// ---------------------------------------------------------------------------
// packed f32x2 helpers
// ---------------------------------------------------------------------------
__device__ __forceinline__ unsigned long long pk2(float x, float y) {
    unsigned long long d;
    asm("mov.b64 %0, {%1, %2};" : "=l"(d) : "f"(x), "f"(y));
    return d;
}
__device__ __forceinline__ void fma2(unsigned long long& a, unsigned long long b,
                                     unsigned long long c) {
    asm("fma.rn.f32x2 %0, %1, %2, %0;" : "+l"(a) : "l"(b), "l"(c));
}
__device__ __forceinline__ unsigned long long add2(unsigned long long a,
                                                   unsigned long long b) {
    unsigned long long d;
    asm("add.rn.f32x2 %0, %1, %2;" : "=l"(d) : "l"(a), "l"(b));
    return d;
}
__device__ __forceinline__ float2 up2(unsigned long long d) {
    float2 r;
    asm("mov.b64 {%0, %1}, %2;" : "=f"(r.x), "=f"(r.y) : "l"(d));
    return r;
}
__device__ __forceinline__ float sigf(float x) { return 1.f / (1.f + expf(-x)); }

// ---------------------------------------------------------------------------
// tf32 helpers (3xTF32 split GEMM)
// ---------------------------------------------------------------------------
__device__ __forceinline__ uint32_t f2tf(float x) {
    uint32_t r;
    asm("cvt.rna.tf32.f32 %0, %1;" : "=r"(r) : "f"(x));
    return r;
}
__device__ __forceinline__ void mma_tf32(float c[4], const uint32_t a[4],
                                         const uint32_t b[2]) {
    asm volatile(
        "mma.sync.aligned.m16n8k8.row.col.f32.tf32.tf32.f32 "
        "{%0,%1,%2,%3}, {%4,%5,%6,%7}, {%8,%9}, {%0,%1,%2,%3};\n"
        : "+f"(c[0]), "+f"(c[1]), "+f"(c[2]), "+f"(c[3])
        : "r"(a[0]), "r"(a[1]), "r"(a[2]), "r"(a[3]), "r"(b[0]), "r"(b[1]));
}

// ---------------------------------------------------------------------------
// grid-wide barrier (release/acquire via threadfence + gen counter)
// ---------------------------------------------------------------------------
__device__ __forceinline__ void gsync(unsigned& gen) {
    __syncthreads();
    if (threadIdx.x == 0) {
        unsigned next = gen + 1;
        __threadfence();
        if (atomicAdd(&g_arrive, 1u) == (unsigned)(NBLK - 1)) {
            g_arrive = 0u;
            __threadfence();
            g_genv = next;
        } else {
            while (g_genv != next) {}
            __threadfence();
        }
        gen = next;
    }
    __syncthreads();
}

// ---------------------------------------------------------------------------
// init
// ---------------------------------------------------------------------------
__global__ void zero_kernel() {
    const size_t n1 = (size_t)(T_STEPS + 1) * BATCH * PROJ;
    const size_t nc = (size_t)BATCH * HID;
    const size_t tot = 2 * n1 + 2 * nc;
    for (size_t i = (size_t)blockIdx.x * blockDim.x + threadIdx.x; i < tot;
         i += (size_t)gridDim.x * blockDim.x) {
        if (i < n1)               g_out1[i] = 0.f;
        else if (i < 2 * n1)      g_out2[i - n1] = 0.f;
        else if (i < 2 * n1 + nc) g_c1[i - 2 * n1] = 0.f;
        else                      g_c2[i - 2 * n1 - nc] = 0.f;
    }
}

// ---------------------------------------------------------------------------
// Fused transpose of all 5 weight matrices in ONE launch.
// ---------------------------------------------------------------------------
__global__ void transpose_all(const float* __restrict__ W_hh1,
                              const float* __restrict__ W_ih2,
                              const float* __restrict__ W_hh2,
                              const float* __restrict__ W_hr1,
                              const float* __restrict__ W_hr2) {
    __shared__ float tile[32][33];
    int bid = blockIdx.x;
    const float* in;
    float* out;
    int rows, ldin, tix;
    if (bid < 8192)       { in = W_hh1; out = g_Wt1;  rows = G4H; ldin = 512;  tix = bid; }
    else if (bid < 16384) { in = W_ih2; out = g_Wt2;  rows = G4H; ldin = 1280; tix = bid - 8192; }
    else if (bid < 24576) { in = W_hh2; out = g_Wt2 + (size_t)512 * G4H;
                                                       rows = G4H; ldin = 512;  tix = bid - 16384; }
    else if (bid < 26624) { in = W_hr1; out = g_Wtr1; rows = 512; ldin = HID;  tix = bid - 24576; }
    else                  { in = W_hr2; out = g_Wtr2; rows = 512; ldin = HID;  tix = bid - 26624; }

    int nbx = rows >> 5;
    int bx = tix % nbx, by = tix / nbx;
    int j0 = bx * 32, k0 = by * 32;
    int tx = threadIdx.x, ty = threadIdx.y;
    #pragma unroll
    for (int i = 0; i < 32; i += 8) {
        int j = j0 + ty + i, k = k0 + tx;
        tile[ty + i][tx] = in[(size_t)j * ldin + k];
    }
    __syncthreads();
    #pragma unroll
    for (int i = 0; i < 32; i += 8) {
        int k = k0 + ty + i, j = j0 + tx;
        out[(size_t)k * rows + j] = tile[tx][ty + i];
    }
}

// ---------------------------------------------------------------------------
// Phase A GEMM on tensor cores: 3xTF32 (fp32-grade accuracy).
// C[m][n] = A[m]·B[n] + bias[n]; A [M][lda], B [N][ldb] row-major (NT GEMM).
// Block tile 128x128, 8 warps = 2(m)x4(n), warp tile 64x32 via m16n8k8.
// ---------------------------------------------------------------------------
__global__ void __launch_bounds__(256)
sgemm_tf32(const float* __restrict__ A, const float* __restrict__ B,
           const float* __restrict__ bias, float* __restrict__ C,
           int K, int lda, int ldb, int boff) {
    __shared__ float Ah[16 * TSTR], Al[16 * TSTR];
    __shared__ float Bh[16 * TSTR], Bl[16 * TSTR];

    const int tid = threadIdx.x;
    const int m0 = blockIdx.y * 128, n0 = blockIdx.x * 128;
    const int warp = tid >> 5, lane = tid & 31;
    const int wm = (warp >> 2) * 64;   // warp m offset: 0 / 64
    const int wn = (warp & 3) * 32;    // warp n offset: 0..96
    const int g  = lane >> 2;          // 0..7
    const int tk = lane & 3;           // 0..3

    float c[4][4][4];
    #pragma unroll
    for (int mt = 0; mt < 4; mt++)
        #pragma unroll
        for (int nt = 0; nt < 4; nt++)
            #pragma unroll
            for (int i = 0; i < 4; i++) c[mt][nt][i] = 0.f;

    const int rr = tid >> 4;   // 0..15 row base for staging
    const int cc = tid & 15;   // k within slab

    for (int k0 = 0; k0 < K; k0 += 16) {
        __syncthreads();   // protect smem from previous slab's readers
        const bool kv = (k0 + cc) < K;
        #pragma unroll
        for (int i = 0; i < 8; i++) {
            int r = rr + i * 16;
            float av = kv ? A[(size_t)(m0 + r) * lda + k0 + cc] : 0.f;
            float bv = kv ? B[(size_t)(n0 + r) * ldb + boff + k0 + cc] : 0.f;
            uint32_t ah = f2tf(av);
            uint32_t bh = f2tf(bv);
            Ah[cc * TSTR + r] = __uint_as_float(ah);
            Al[cc * TSTR + r] = __uint_as_float(f2tf(av - __uint_as_float(ah)));
            Bh[cc * TSTR + r] = __uint_as_float(bh);
            Bl[cc * TSTR + r] = __uint_as_float(f2tf(bv - __uint_as_float(bh)));
        }
        __syncthreads();

        #pragma unroll
        for (int ks = 0; ks < 16; ks += 8) {
            const int kk = ks + tk;
            uint32_t ahf[4][4], alf[4][4], bhf[4][2], blf[4][2];
            #pragma unroll
            for (int mt = 0; mt < 4; mt++) {
                int rb = wm + mt * 16 + g;
                ahf[mt][0] = __float_as_uint(Ah[kk * TSTR + rb]);
                ahf[mt][1] = __float_as_uint(Ah[kk * TSTR + rb + 8]);
                ahf[mt][2] = __float_as_uint(Ah[(kk + 4) * TSTR + rb]);
                ahf[mt][3] = __float_as_uint(Ah[(kk + 4) * TSTR + rb + 8]);
                alf[mt][0] = __float_as_uint(Al[kk * TSTR + rb]);
                alf[mt][1] = __float_as_uint(Al[kk * TSTR + rb + 8]);
                alf[mt][2] = __float_as_uint(Al[(kk + 4) * TSTR + rb]);
                alf[mt][3] = __float_as_uint(Al[(kk + 4) * TSTR + rb + 8]);
            }
            #pragma unroll
            for (int nt = 0; nt < 4; nt++) {
                int nb = wn + nt * 8 + g;
                bhf[nt][0] = __float_as_uint(Bh[kk * TSTR + nb]);
                bhf[nt][1] = __float_as_uint(Bh[(kk + 4) * TSTR + nb]);
                blf[nt][0] = __float_as_uint(Bl[kk * TSTR + nb]);
                blf[nt][1] = __float_as_uint(Bl[(kk + 4) * TSTR + nb]);
            }
            #pragma unroll
            for (int mt = 0; mt < 4; mt++)
                #pragma unroll
                for (int nt = 0; nt < 4; nt++) {
                    mma_tf32(c[mt][nt], ahf[mt], bhf[nt]);   // hi*hi
                    mma_tf32(c[mt][nt], ahf[mt], blf[nt]);   // hi*lo
                    mma_tf32(c[mt][nt], alf[mt], bhf[nt]);   // lo*hi
                }
        }
    }

    // epilogue: add bias, streaming stores (xg consumed once later)
    #pragma unroll
    for (int nt = 0; nt < 4; nt++) {
        int col = n0 + wn + nt * 8 + 2 * tk;
        float b0 = bias[col], b1 = bias[col + 1];
        #pragma unroll
        for (int mt = 0; mt < 4; mt++) {
            int row0 = m0 + wm + mt * 16 + g;
            float2 v0 = {c[mt][nt][0] + b0, c[mt][nt][1] + b1};
            float2 v1 = {c[mt][nt][2] + b0, c[mt][nt][3] + b1};
            __stcs((float2*)(C + (size_t)row0 * G4H + col), v0);
            __stcs((float2*)(C + (size_t)(row0 + 8) * G4H + col), v1);
        }
    }
}

// ---------------------------------------------------------------------------
// Stage h into hsf[k*HSTR + b]. KROWS rows; src1 covers k<512, src2 the rest.
// ---------------------------------------------------------------------------
template <int KROWS>
__device__ __forceinline__ void stage_h(const float* __restrict__ src1,
                                        const float* __restrict__ src2,
                                        float* hsf) {
    const int tid = threadIdx.x;
    for (int idx = tid; idx < 4 * KROWS; idx += 512) {
        int bb, k;
        if (KROWS == 512) { bb = idx >> 9;  k = idx & 511;  }
        else              { bb = idx >> 10; k = idx & 1023; }
        int b0 = 4 * bb;
        const float* s = (KROWS == 512 || k < 512) ? (src1 + k) : (src2 + (k - 512));
        float4 v;
        v.x = s[(b0 + 0) * PROJ];
        v.y = s[(b0 + 1) * PROJ];
        v.z = s[(b0 + 2) * PROJ];
        v.w = s[(b0 + 3) * PROJ];
        *(float4*)&hsf[k * HSTR + 4 * bb] = v;
    }
}

// ---------------------------------------------------------------------------
// Gate core: 512 threads, 8-way K split, micro-tile 8 rows x 4 batches.
// ---------------------------------------------------------------------------
template <int KTOT>
__device__ __forceinline__ void gate_core(
    const float* __restrict__ Wt, const float* __restrict__ xg,
    float& cref, float* __restrict__ gh, float* __restrict__ cglob, bool last,
    const float* hsf, ulonglong2* redu2, float* zbuf)
{
    const int tid = threadIdx.x;
    const int ksub = tid >> 6;            // 0..7
    const int r    = tid & 63;            // 0..63
    const int rowg = r >> 2;              // 0..15
    const int bg   = (r & 3) << 2;        // 0,4,8,12
    const int gate = rowg >> 2;           // 0..3
    const int j0   = blockIdx.x * 32;
    const int jj   = (rowg & 3) << 3;     // 0,8,16,24
    const int row8 = gate * HID + j0 + jj;
    const int kh   = KTOT / 8;
    const int kbeg = ksub * kh;

    const ulonglong2* wp = (const ulonglong2*)(Wt + (size_t)kbeg * G4H + row8);
    const float* hp = hsf + (size_t)kbeg * HSTR + bg;

    unsigned long long acc[4][4];
    #pragma unroll
    for (int i = 0; i < 4; i++)
        #pragma unroll
        for (int j = 0; j < 4; j++) acc[i][j] = 0ull;

    #pragma unroll 8
    for (int k = 0; k < kh; k++) {
        ulonglong2 wa = wp[(size_t)k * (G4H / 4)];
        ulonglong2 wb = wp[(size_t)k * (G4H / 4) + 1];
        float4 h = *(const float4*)(hp + k * HSTR);
        unsigned long long h0 = pk2(h.x, h.x), h1 = pk2(h.y, h.y);
        unsigned long long h2 = pk2(h.z, h.z), h3 = pk2(h.w, h.w);
        fma2(acc[0][0], wa.x, h0); fma2(acc[0][1], wa.x, h1);
        fma2(acc[0][2], wa.x, h2); fma2(acc[0][3], wa.x, h3);
        fma2(acc[1][0], wa.y, h0); fma2(acc[1][1], wa.y, h1);
        fma2(acc[1][2], wa.y, h2); fma2(acc[1][3], wa.y, h3);
        fma2(acc[2][0], wb.x, h0); fma2(acc[2][1], wb.x, h1);
        fma2(acc[2][2], wb.x, h2); fma2(acc[2][3], wb.x, h3);
        fma2(acc[3][0], wb.y, h0); fma2(acc[3][1], wb.y, h1);
        fma2(acc[3][2], wb.y, h2); fma2(acc[3][3], wb.y, h3);
    }

    if (ksub > 0) {
        ulonglong2* dst = redu2 + (size_t)(ksub - 1) * 512 + r;
        #pragma unroll
        for (int rp = 0; rp < 4; rp++)
            #pragma unroll
            for (int bh = 0; bh < 2; bh++)
                dst[(rp * 2 + bh) * 64] = make_ulonglong2(acc[rp][2 * bh],
                                                          acc[rp][2 * bh + 1]);
    }
    __syncthreads();

    if (ksub == 0) {
        #pragma unroll
        for (int g = 0; g < 7; g++) {
            const ulonglong2* src = redu2 + (size_t)g * 512 + r;
            #pragma unroll
            for (int rp = 0; rp < 4; rp++)
                #pragma unroll
                for (int bh = 0; bh < 2; bh++) {
                    ulonglong2 v = src[(rp * 2 + bh) * 64];
                    acc[rp][2 * bh]     = add2(acc[rp][2 * bh], v.x);
                    acc[rp][2 * bh + 1] = add2(acc[rp][2 * bh + 1], v.y);
                }
        }
        #pragma unroll
        for (int bi = 0; bi < 4; bi++) {
            const float* xr = xg + (size_t)(bg + bi) * G4H + row8;
            float4 x0 = __ldcs((const float4*)xr);
            float4 x1 = __ldcs((const float4*)(xr + 4));
            float2 a0 = up2(acc[0][bi]), a1 = up2(acc[1][bi]);
            float2 a2 = up2(acc[2][bi]), a3 = up2(acc[3][bi]);
            float4 z0 = {a0.x + x0.x, a0.y + x0.y, a1.x + x0.z, a1.y + x0.w};
            float4 z1 = {a2.x + x1.x, a2.y + x1.y, a3.x + x1.z, a3.y + x1.w};
            float* zb = &zbuf[gate * 512 + (bg + bi) * 32 + jj];
            *(float4*)zb = z0;
            *(float4*)(zb + 4) = z1;
        }
    }
    __syncthreads();

    {
        int b = tid >> 5, jl = tid & 31;
        float zi = zbuf[0 * 512 + b * 32 + jl];
        float zf = zbuf[1 * 512 + b * 32 + jl];
        float zg = zbuf[2 * 512 + b * 32 + jl];
        float zo = zbuf[3 * 512 + b * 32 + jl];
        size_t off = (size_t)b * HID + j0 + jl;
        float cn = sigf(zf) * cref + sigf(zi) * tanhf(zg);
        cref = cn;
        gh[off] = sigf(zo) * tanhf(cn);
        if (last) cglob[off] = cn;
    }
}

// ---------------------------------------------------------------------------
// Proj staging + core.
// ---------------------------------------------------------------------------
__device__ __forceinline__ void stage_g(const float* __restrict__ gh,
                                        int kb, float* gpf) {
    const int tid = threadIdx.x;
    int bb = tid >> 7, k = tid & 127;
    int b0 = 4 * bb;
    float4 v;
    v.x = __ldcs(gh + (size_t)(b0 + 0) * HID + kb + k);
    v.y = __ldcs(gh + (size_t)(b0 + 1) * HID + kb + k);
    v.z = __ldcs(gh + (size_t)(b0 + 2) * HID + kb + k);
    v.w = __ldcs(gh + (size_t)(b0 + 3) * HID + kb + k);
    *(float4*)&gpf[k * HSTR + 4 * bb] = v;
}

__device__ __forceinline__ void proj_core(
    const float* gpf, const float* __restrict__ Wtr,
    float* __restrict__ hout, int p0, int kb, unsigned long long* predu)
{
    const int tid = threadIdx.x;
    const int ks = tid >> 7, r = tid & 127;
    const int rowg = r >> 2, bg = (r & 3) << 2;
    const int p4 = p0 + rowg * 4;
    const int kbeg = ks * 32;

    const ulonglong2* wp = (const ulonglong2*)(Wtr + (size_t)(kb + kbeg) * PROJ + p4);
    const float* hp = gpf + kbeg * HSTR + bg;

    unsigned long long acc[2][4];
    #pragma unroll
    for (int i = 0; i < 2; i++)
        #pragma unroll
        for (int j = 0; j < 4; j++) acc[i][j] = 0ull;

    #pragma unroll 8
    for (int k = 0; k < 32; k++) {
        ulonglong2 w = wp[(size_t)k * (PROJ / 4)];
        float4 h = *(const float4*)(hp + k * HSTR);
        unsigned long long h0 = pk2(h.x, h.x), h1 = pk2(h.y, h.y);
        unsigned long long h2 = pk2(h.z, h.z), h3 = pk2(h.w, h.w);
        fma2(acc[0][0], w.x, h0); fma2(acc[1][0], w.y, h0);
        fma2(acc[0][1], w.x, h1); fma2(acc[1][1], w.y, h1);
        fma2(acc[0][2], w.x, h2); fma2(acc[1][2], w.y, h2);
        fma2(acc[0][3], w.x, h3); fma2(acc[1][3], w.y, h3);
    }

    if (ks > 0) {
        unsigned long long* dst = predu + (size_t)(ks - 1) * 1152 + r * 9;
        #pragma unroll
        for (int rp = 0; rp < 2; rp++)
            #pragma unroll
            for (int bi = 0; bi < 4; bi++) dst[rp * 4 + bi] = acc[rp][bi];
    }
    __syncthreads();

    if (ks == 0) {
        #pragma unroll
        for (int g = 0; g < 3; g++) {
            const unsigned long long* src = predu + (size_t)g * 1152 + r * 9;
            #pragma unroll
            for (int rp = 0; rp < 2; rp++)
                #pragma unroll
                for (int bi = 0; bi < 4; bi++)
                    acc[rp][bi] = add2(acc[rp][bi], src[rp * 4 + bi]);
        }
        #pragma unroll
        for (int bi = 0; bi < 4; bi++) {
            float2 a0 = up2(acc[0][bi]);
            float2 a1 = up2(acc[1][bi]);
            float* o = hout + (size_t)(bg + bi) * PROJ + p4;
            atomicAdd(o + 0, a0.x);
            atomicAdd(o + 1, a0.y);
            atomicAdd(o + 2, a1.x);
            atomicAdd(o + 3, a1.y);
        }
    }
}

// ---------------------------------------------------------------------------
// Persistent recurrence with layer pipelining.
// ---------------------------------------------------------------------------
__global__ void __launch_bounds__(512, 1) recurrence_kernel() {
    extern __shared__ float smem[];
    float* hsf  = smem;
    ulonglong2* redu2 = (ulonglong2*)(smem + SM_RED_OFF_F);
    float* zbuf = smem + SM_Z_OFF_F;
    float* gpf1 = smem;
    float* gpf2 = smem + 2560;
    unsigned long long* predu = (unsigned long long*)(smem + 5120);

    const int pt = blockIdx.x & 3;
    const int kc = blockIdx.x >> 2;
    const int p0 = pt * 128, kb = kc * 128;

    unsigned gen = g_genv;
    float c1r = 0.f, c2r = 0.f;

    // prologue: G1(0)
    stage_h<512>(g_out1, nullptr, hsf);
    __syncthreads();
    gate_core<512>(g_Wt1, g_xg1, c1r, g_g1h, g_c1, false, hsf, redu2, zbuf);
    gsync(gen);
    // P1(0) -> out1[1]
    stage_g(g_g1h, kb, gpf1);
    __syncthreads();
    proj_core(gpf1, g_Wtr1, g_out1 + (size_t)1 * (BATCH * PROJ), p0, kb, predu);
    gsync(gen);

    for (int t = 0; t < T_STEPS - 1; t++) {
        stage_h<1024>(g_out1 + (size_t)(t + 1) * (BATCH * PROJ),
                      g_out2 + (size_t)t * (BATCH * PROJ), hsf);
        __syncthreads();
        gate_core<512>(g_Wt1, g_xg1 + (size_t)(t + 1) * BATCH * G4H,
                       c1r, g_g1h, g_c1, (t + 1 == T_STEPS - 1),
                       hsf, redu2, zbuf);
        __syncthreads();
        gate_core<1024>(g_Wt2, g_xg2 + (size_t)t * BATCH * G4H,
                        c2r, g_g2h, g_c2, false, hsf, redu2, zbuf);
        gsync(gen);
        stage_g(g_g1h, kb, gpf1);
        stage_g(g_g2h, kb, gpf2);
        __syncthreads();
        proj_core(gpf1, g_Wtr1, g_out1 + (size_t)(t + 2) * (BATCH * PROJ),
                  p0, kb, predu);
        __syncthreads();
        proj_core(gpf2, g_Wtr2, g_out2 + (size_t)(t + 1) * (BATCH * PROJ),
                  p0, kb, predu);
        gsync(gen);
    }

    // tail: G2(255), P2(255)
    {
        int t = T_STEPS - 1;
        stage_h<1024>(g_out1 + (size_t)(t + 1) * (BATCH * PROJ),
                      g_out2 + (size_t)t * (BATCH * PROJ), hsf);
        __syncthreads();
        gate_core<1024>(g_Wt2, g_xg2 + (size_t)t * BATCH * G4H,
                        c2r, g_g2h, g_c2, true, hsf, redu2, zbuf);
        gsync(gen);
        stage_g(g_g2h, kb, gpf1);
        __syncthreads();
        proj_core(gpf1, g_Wtr2, g_out2 + (size_t)(t + 1) * (BATCH * PROJ),
                  p0, kb, predu);
    }
}

// ---------------------------------------------------------------------------
// Packed-sequence bookkeeping
// ---------------------------------------------------------------------------
__global__ void counts_kernel(const int* __restrict__ lens) {
    int t = threadIdx.x;
    int c = 0;
    #pragma unroll
    for (int b = 0; b < BATCH; b++) c += (lens[b] > t) ? 1 : 0;
    g_counts[t] = c;
    __syncthreads();
    if (t == 0) {
        int s = 0;
        for (int i = 0; i < T_STEPS; i++) { g_offsets[i] = s; s += g_counts[i]; }
        g_offsets[T_STEPS] = s;
    }
}

// ---------------------------------------------------------------------------
// Heads: one warp per packed token
// ---------------------------------------------------------------------------
__global__ void __launch_bounds__(512) heads_kernel(
    const float* __restrict__ Wp, const float* __restrict__ bp,
    const float* __restrict__ Wa, const float* __restrict__ ba,
    float* __restrict__ out, int total) {
    const int t = blockIdx.x;
    const int w = threadIdx.x >> 5;
    const int lane = threadIdx.x & 31;
    if (w >= g_counts[t]) return;
    const int b = w;
    const int tok = g_offsets[t] + b;

    const float* o1 = g_out1 + (size_t)(t + 1) * (BATCH * PROJ) + (size_t)b * PROJ;
    const float* o2 = g_out2 + (size_t)(t + 1) * (BATCH * PROJ) + (size_t)b * PROJ;
    float v[16];
    #pragma unroll
    for (int i = 0; i < 16; i++) v[i] = o1[lane + 32 * i] + o2[lane + 32 * i];

    __shared__ float sp[16][20];
    __shared__ float sa[16][20];
    #pragma unroll
    for (int o = 0; o < 20; o++) {
        float s1 = 0.f, s2 = 0.f;
        #pragma unroll
        for (int i = 0; i < 16; i++) {
            float x = v[i];
            s1 = fmaf(x, Wp[o * PROJ + lane + 32 * i], s1);
            s2 = fmaf(x, Wa[o * PROJ + lane + 32 * i], s2);
        }
        #pragma unroll
        for (int off = 16; off; off >>= 1) {
            s1 += __shfl_xor_sync(0xffffffffu, s1, off);
            s2 += __shfl_xor_sync(0xffffffffu, s2, off);
        }
        if (lane == 0) { sp[w][o] = s1 + bp[o]; sa[w][o] = s2 + ba[o]; }
    }
    __syncwarp();
    if (lane == 0) {
        float m = -1e30f;
        #pragma unroll
        for (int o = 0; o < 20; o++) m = fmaxf(m, sp[w][o]);
        float e[20], sum = 0.f;
        #pragma unroll
        for (int o = 0; o < 20; o++) { e[o] = expf(sp[w][o] - m); sum += e[o]; }
        float inv = 1.f / sum;
        float* aa = out + (size_t)total * 20;
        #pragma unroll
        for (int o = 0; o < 20; o++) {
            out[(size_t)tok * 20 + o] = e[o] * inv;
            aa[(size_t)tok * 20 + o]  = sa[w][o];
        }
    }
}

// ---------------------------------------------------------------------------
// Final states: h1, c1, h2, c2
// ---------------------------------------------------------------------------
__global__ void finalize_kernel(float* __restrict__ out, int total) {
    const size_t base = (size_t)total * 40;
    const int nH = BATCH * PROJ;
    const int nC = BATCH * HID;
    int idx = blockIdx.x * blockDim.x + threadIdx.x;
    if (idx >= 2 * (nH + nC)) return;
    float v;
    if (idx < nH)                v = g_out1[(size_t)T_STEPS * nH + idx];
    else if (idx < nH + nC)      v = g_c1[idx - nH];
    else if (idx < 2 * nH + nC)  v = g_out2[(size_t)T_STEPS * nH + (idx - nH - nC)];
    else                         v = g_c2[idx - 2 * nH - nC];
    out[base + idx] = v;
}

// ---------------------------------------------------------------------------
// Host launch
// ---------------------------------------------------------------------------
extern "C" void kernel_launch(void* const* d_in, const int* in_sizes, int n_in,
                              void* d_out, int out_size) {
    const float* uncon  = (const float*)d_in[0];
    const float* con    = (const float*)d_in[1];
    const int*   lens   = (const int*)d_in[2];
    const float* W_ih1  = (const float*)d_in[3];
    const float* b1     = (const float*)d_in[4];
    const float* W_hh1  = (const float*)d_in[5];
    const float* W_hr1  = (const float*)d_in[6];
    const float* W_ih2  = (const float*)d_in[7];
    const float* b2     = (const float*)d_in[8];
    const float* W_hh2  = (const float*)d_in[9];
    const float* W_hr2  = (const float*)d_in[10];
    const float* W_pssm = (const float*)d_in[11];
    const float* b_pssm = (const float*)d_in[12];
    const float* W_aa   = (const float*)d_in[13];
    const float* b_aa   = (const float*)d_in[14];
    float* out = (float*)d_out;

    const int total = (out_size - 2 * (BATCH * PROJ + BATCH * HID)) / 40;

    float *p_xg1, *p_xg2;
    cudaGetSymbolAddress((void**)&p_xg1, g_xg1);
    cudaGetSymbolAddress((void**)&p_xg2, g_xg2);

    cudaFuncSetAttribute(recurrence_kernel,
                         cudaFuncAttributeMaxDynamicSharedMemorySize, SM_TOTAL_B);

    zero_kernel<<<2048, 256>>>();
    transpose_all<<<28672, dim3(32, 8)>>>(W_hh1, W_ih2, W_hh2, W_hr1, W_hr2);
    // Phase A on tensor cores (3xTF32)
    sgemm_tf32<<<dim3(G4H / 128, (T_STEPS * BATCH) / 128), 256>>>(
        uncon, W_ih1, b1, p_xg1, F1, F1, F1, 0);
    sgemm_tf32<<<dim3(G4H / 128, (T_STEPS * BATCH) / 128), 256>>>(
        con, W_ih2, b2, p_xg2, F2CON, F2CON, 1280, 512);
    counts_kernel<<<1, 256>>>(lens);
    recurrence_kernel<<<NBLK, 512, SM_TOTAL_B>>>();
    heads_kernel<<<T_STEPS, 512>>>(W_pssm, b_pssm, W_aa, b_aa, out, total);
    finalize_kernel<<<(2 * (BATCH * PROJ + BATCH * HID) + 255) / 256, 256>>>(out, total);
}

// round 11
// speedup vs baseline: 1.0607x; 1.0244x over previous
#include <cuda_runtime.h>
#include <math.h>
#include <stdint.h>

// ---------------------------------------------------------------------------
// Problem constants
// ---------------------------------------------------------------------------
#define T_STEPS 256
#define BATCH   16
#define HID     4096          // H
#define PROJ    512           // P
#define G4H     16384         // 4*H
#define F1      532
#define F2CON   768           // con_x features (1280-512)
#define NBLK    128           // persistent grid size
#define HSTR    20            // padded smem row stride (floats) for h tiles

#define TSTR 136              // tf32 sgemm smem stride (floats)

// persistent-kernel dynamic smem (floats):
//  gate phase: hsf [0,20480) | redu1 f[20480,36864) | redu2 f[36864,53248)
//              zbuf1 aliases smem[0,2048), zbuf2 [2048,4096) (hsf dead by then)
//  proj phase: gpf1 [0,2560) | gpf2 [2560,5120) | predu1 f[5120,14336)
//              predu2 f[14336,23552)
#define SM_TOTAL_F 53248
#define SM_TOTAL_B (SM_TOTAL_F * 4)     // 212992

// ---------------------------------------------------------------------------
// Device scratch (static only — no cudaMalloc allowed)
// ---------------------------------------------------------------------------
__device__ float g_xg1[(size_t)T_STEPS * BATCH * G4H];   // 268 MB
__device__ float g_xg2[(size_t)T_STEPS * BATCH * G4H];   // 268 MB
__device__ float g_Wt1[(size_t)512 * G4H];               // W_hh1^T  [k][row]
__device__ float g_Wt2[(size_t)1024 * G4H];              // [W_ih2[:,:512]; W_hh2]^T
__device__ float g_Wtr1[(size_t)HID * PROJ];             // W_hr1^T [k][p]
__device__ float g_Wtr2[(size_t)HID * PROJ];
__device__ float g_out1[(size_t)(T_STEPS + 1) * BATCH * PROJ];
__device__ float g_out2[(size_t)(T_STEPS + 1) * BATCH * PROJ];
__device__ float g_c1[BATCH * HID];
__device__ float g_c2[BATCH * HID];
__device__ float g_g1h[BATCH * HID];
__device__ float g_g2h[BATCH * HID];
__device__ int   g_counts[T_STEPS];
__device__ int   g_offsets[T_STEPS + 1];

__device__ volatile unsigned g_genv;   // monotonic across replays
__device__ unsigned g_arrive;          // self-resetting

// ---------------------------------------------------------------------------
// packed f32x2 helpers
// ---------------------------------------------------------------------------
__device__ __forceinline__ unsigned long long pk2(float x, float y) {
    unsigned long long d;
    asm("mov.b64 %0, {%1, %2};" : "=l"(d) : "f"(x), "f"(y));
    return d;
}
__device__ __forceinline__ void fma2(unsigned long long& a, unsigned long long b,
                                     unsigned long long c) {
    asm("fma.rn.f32x2 %0, %1, %2, %0;" : "+l"(a) : "l"(b), "l"(c));
}
__device__ __forceinline__ unsigned long long add2(unsigned long long a,
                                                   unsigned long long b) {
    unsigned long long d;
    asm("add.rn.f32x2 %0, %1, %2;" : "=l"(d) : "l"(a), "l"(b));
    return d;
}
__device__ __forceinline__ float2 up2(unsigned long long d) {
    float2 r;
    asm("mov.b64 {%0, %1}, %2;" : "=f"(r.x), "=f"(r.y) : "l"(d));
    return r;
}
__device__ __forceinline__ float sigf(float x) { return 1.f / (1.f + expf(-x)); }

// ---------------------------------------------------------------------------
// tf32 helpers (3xTF32 split GEMM)
// ---------------------------------------------------------------------------
__device__ __forceinline__ uint32_t f2tf(float x) {
    uint32_t r;
    asm("cvt.rna.tf32.f32 %0, %1;" : "=r"(r) : "f"(x));
    return r;
}
__device__ __forceinline__ void mma_tf32(float c[4], const uint32_t a[4],
                                         const uint32_t b[2]) {
    asm volatile(
        "mma.sync.aligned.m16n8k8.row.col.f32.tf32.tf32.f32 "
        "{%0,%1,%2,%3}, {%4,%5,%6,%7}, {%8,%9}, {%0,%1,%2,%3};\n"
        : "+f"(c[0]), "+f"(c[1]), "+f"(c[2]), "+f"(c[3])
        : "r"(a[0]), "r"(a[1]), "r"(a[2]), "r"(a[3]), "r"(b[0]), "r"(b[1]));
}

// ---------------------------------------------------------------------------
// grid-wide barrier
// ---------------------------------------------------------------------------
__device__ __forceinline__ void gsync(unsigned& gen) {
    __syncthreads();
    if (threadIdx.x == 0) {
        unsigned next = gen + 1;
        __threadfence();
        if (atomicAdd(&g_arrive, 1u) == (unsigned)(NBLK - 1)) {
            g_arrive = 0u;
            __threadfence();
            g_genv = next;
        } else {
            while (g_genv != next) {}
            __threadfence();
        }
        gen = next;
    }
    __syncthreads();
}

// ---------------------------------------------------------------------------
// Fused prep: weight transposes + state zeroing + packed-seq counts, 1 launch.
// blocks [0,28672): transpose; 28672: counts; (28672,30721): zero.
// ---------------------------------------------------------------------------
__global__ void prep_kernel(const float* __restrict__ W_hh1,
                            const float* __restrict__ W_ih2,
                            const float* __restrict__ W_hh2,
                            const float* __restrict__ W_hr1,
                            const float* __restrict__ W_hr2,
                            const int* __restrict__ lens) {
    int bid = blockIdx.x;
    int tid = threadIdx.x;
    if (bid < 28672) {
        __shared__ float tile[32][33];
        const float* in;
        float* out;
        int rows, ldin, tix;
        if (bid < 8192)       { in = W_hh1; out = g_Wt1;  rows = G4H; ldin = 512;  tix = bid; }
        else if (bid < 16384) { in = W_ih2; out = g_Wt2;  rows = G4H; ldin = 1280; tix = bid - 8192; }
        else if (bid < 24576) { in = W_hh2; out = g_Wt2 + (size_t)512 * G4H;
                                                           rows = G4H; ldin = 512;  tix = bid - 16384; }
        else if (bid < 26624) { in = W_hr1; out = g_Wtr1; rows = 512; ldin = HID;  tix = bid - 24576; }
        else                  { in = W_hr2; out = g_Wtr2; rows = 512; ldin = HID;  tix = bid - 26624; }
        int nbx = rows >> 5;
        int bx = tix % nbx, by = tix / nbx;
        int j0 = bx * 32, k0 = by * 32;
        int tx = tid & 31, ty = tid >> 5;
        #pragma unroll
        for (int i = 0; i < 32; i += 8) {
            int j = j0 + ty + i, k = k0 + tx;
            tile[ty + i][tx] = in[(size_t)j * ldin + k];
        }
        __syncthreads();
        #pragma unroll
        for (int i = 0; i < 32; i += 8) {
            int k = k0 + ty + i, j = j0 + tx;
            out[(size_t)k * rows + j] = tile[tx][ty + i];
        }
    } else if (bid == 28672) {
        int t = tid;
        int c = 0;
        #pragma unroll
        for (int b = 0; b < BATCH; b++) c += (lens[b] > t) ? 1 : 0;
        g_counts[t] = c;
        __syncthreads();
        if (t == 0) {
            int s = 0;
            for (int i = 0; i < T_STEPS; i++) { g_offsets[i] = s; s += g_counts[i]; }
            g_offsets[T_STEPS] = s;
        }
    } else {
        const size_t n1 = (size_t)(T_STEPS + 1) * BATCH * PROJ;
        const size_t nc = (size_t)BATCH * HID;
        const size_t tot = 2 * n1 + 2 * nc;
        size_t base = (size_t)(bid - 28673) * 256 + tid;
        for (size_t i = base; i < tot; i += (size_t)2048 * 256) {
            if (i < n1)               g_out1[i] = 0.f;
            else if (i < 2 * n1)      g_out2[i - n1] = 0.f;
            else if (i < 2 * n1 + nc) g_c1[i - 2 * n1] = 0.f;
            else                      g_c2[i - 2 * n1 - nc] = 0.f;
        }
    }
}

// ---------------------------------------------------------------------------
// Phase A GEMM on tensor cores: 3xTF32 (fp32-grade accuracy).
// ---------------------------------------------------------------------------
__global__ void __launch_bounds__(256)
sgemm_tf32(const float* __restrict__ A, const float* __restrict__ B,
           const float* __restrict__ bias, float* __restrict__ C,
           int K, int lda, int ldb, int boff) {
    __shared__ float Ah[16 * TSTR], Al[16 * TSTR];
    __shared__ float Bh[16 * TSTR], Bl[16 * TSTR];

    const int tid = threadIdx.x;
    const int m0 = blockIdx.y * 128, n0 = blockIdx.x * 128;
    const int warp = tid >> 5, lane = tid & 31;
    const int wm = (warp >> 2) * 64;
    const int wn = (warp & 3) * 32;
    const int g  = lane >> 2;
    const int tk = lane & 3;

    float c[4][4][4];
    #pragma unroll
    for (int mt = 0; mt < 4; mt++)
        #pragma unroll
        for (int nt = 0; nt < 4; nt++)
            #pragma unroll
            for (int i = 0; i < 4; i++) c[mt][nt][i] = 0.f;

    const int rr = tid >> 4;
    const int cc = tid & 15;

    for (int k0 = 0; k0 < K; k0 += 16) {
        __syncthreads();
        const bool kv = (k0 + cc) < K;
        #pragma unroll
        for (int i = 0; i < 8; i++) {
            int r = rr + i * 16;
            float av = kv ? A[(size_t)(m0 + r) * lda + k0 + cc] : 0.f;
            float bv = kv ? B[(size_t)(n0 + r) * ldb + boff + k0 + cc] : 0.f;
            uint32_t ah = f2tf(av);
            uint32_t bh = f2tf(bv);
            Ah[cc * TSTR + r] = __uint_as_float(ah);
            Al[cc * TSTR + r] = __uint_as_float(f2tf(av - __uint_as_float(ah)));
            Bh[cc * TSTR + r] = __uint_as_float(bh);
            Bl[cc * TSTR + r] = __uint_as_float(f2tf(bv - __uint_as_float(bh)));
        }
        __syncthreads();

        #pragma unroll
        for (int ks = 0; ks < 16; ks += 8) {
            const int kk = ks + tk;
            uint32_t ahf[4][4], alf[4][4], bhf[4][2], blf[4][2];
            #pragma unroll
            for (int mt = 0; mt < 4; mt++) {
                int rb = wm + mt * 16 + g;
                ahf[mt][0] = __float_as_uint(Ah[kk * TSTR + rb]);
                ahf[mt][1] = __float_as_uint(Ah[kk * TSTR + rb + 8]);
                ahf[mt][2] = __float_as_uint(Ah[(kk + 4) * TSTR + rb]);
                ahf[mt][3] = __float_as_uint(Ah[(kk + 4) * TSTR + rb + 8]);
                alf[mt][0] = __float_as_uint(Al[kk * TSTR + rb]);
                alf[mt][1] = __float_as_uint(Al[kk * TSTR + rb + 8]);
                alf[mt][2] = __float_as_uint(Al[(kk + 4) * TSTR + rb]);
                alf[mt][3] = __float_as_uint(Al[(kk + 4) * TSTR + rb + 8]);
            }
            #pragma unroll
            for (int nt = 0; nt < 4; nt++) {
                int nb = wn + nt * 8 + g;
                bhf[nt][0] = __float_as_uint(Bh[kk * TSTR + nb]);
                bhf[nt][1] = __float_as_uint(Bh[(kk + 4) * TSTR + nb]);
                blf[nt][0] = __float_as_uint(Bl[kk * TSTR + nb]);
                blf[nt][1] = __float_as_uint(Bl[(kk + 4) * TSTR + nb]);
            }
            #pragma unroll
            for (int mt = 0; mt < 4; mt++)
                #pragma unroll
                for (int nt = 0; nt < 4; nt++) {
                    mma_tf32(c[mt][nt], ahf[mt], bhf[nt]);
                    mma_tf32(c[mt][nt], ahf[mt], blf[nt]);
                    mma_tf32(c[mt][nt], alf[mt], bhf[nt]);
                }
        }
    }

    #pragma unroll
    for (int nt = 0; nt < 4; nt++) {
        int col = n0 + wn + nt * 8 + 2 * tk;
        float b0 = bias[col], b1 = bias[col + 1];
        #pragma unroll
        for (int mt = 0; mt < 4; mt++) {
            int row0 = m0 + wm + mt * 16 + g;
            float2 v0 = {c[mt][nt][0] + b0, c[mt][nt][1] + b1};
            float2 v1 = {c[mt][nt][2] + b0, c[mt][nt][3] + b1};
            __stcs((float2*)(C + (size_t)row0 * G4H + col), v0);
            __stcs((float2*)(C + (size_t)(row0 + 8) * G4H + col), v1);
        }
    }
}

// ---------------------------------------------------------------------------
// Stage h into hsf[k*HSTR + b]. KROWS rows; src1 covers k<512, src2 the rest.
// ---------------------------------------------------------------------------
template <int KROWS>
__device__ __forceinline__ void stage_h(const float* __restrict__ src1,
                                        const float* __restrict__ src2,
                                        float* hsf) {
    const int tid = threadIdx.x;
    for (int idx = tid; idx < 4 * KROWS; idx += 512) {
        int bb, k;
        if (KROWS == 512) { bb = idx >> 9;  k = idx & 511;  }
        else              { bb = idx >> 10; k = idx & 1023; }
        int b0 = 4 * bb;
        const float* s = (KROWS == 512 || k < 512) ? (src1 + k) : (src2 + (k - 512));
        float4 v;
        v.x = s[(b0 + 0) * PROJ];
        v.y = s[(b0 + 1) * PROJ];
        v.z = s[(b0 + 2) * PROJ];
        v.w = s[(b0 + 3) * PROJ];
        *(float4*)&hsf[k * HSTR + 4 * bb] = v;
    }
}

// ---------------------------------------------------------------------------
// Gate main loop: 8-way K split, micro-tile 8 rows x 4 batches.
// NO internal syncs; ALL 8 ksub groups write partials to redu.
// ---------------------------------------------------------------------------
template <int KTOT>
__device__ __forceinline__ void gate_loop(const float* __restrict__ Wt,
                                          const float* hsf, ulonglong2* redu) {
    const int tid = threadIdx.x;
    const int ksub = tid >> 6;            // 0..7
    const int r    = tid & 63;            // 0..63
    const int rowg = r >> 2;              // 0..15
    const int bg   = (r & 3) << 2;        // 0,4,8,12
    const int gate = rowg >> 2;           // 0..3
    const int j0   = blockIdx.x * 32;
    const int jj   = (rowg & 3) << 3;     // 0,8,16,24
    const int row8 = gate * HID + j0 + jj;
    const int kh   = KTOT / 8;
    const int kbeg = ksub * kh;

    const ulonglong2* wp = (const ulonglong2*)(Wt + (size_t)kbeg * G4H + row8);
    const float* hp = hsf + (size_t)kbeg * HSTR + bg;

    unsigned long long acc[4][4];
    #pragma unroll
    for (int i = 0; i < 4; i++)
        #pragma unroll
        for (int j = 0; j < 4; j++) acc[i][j] = 0ull;

    #pragma unroll 8
    for (int k = 0; k < kh; k++) {
        ulonglong2 wa = wp[(size_t)k * (G4H / 4)];
        ulonglong2 wb = wp[(size_t)k * (G4H / 4) + 1];
        float4 h = *(const float4*)(hp + k * HSTR);
        unsigned long long h0 = pk2(h.x, h.x), h1 = pk2(h.y, h.y);
        unsigned long long h2 = pk2(h.z, h.z), h3 = pk2(h.w, h.w);
        fma2(acc[0][0], wa.x, h0); fma2(acc[0][1], wa.x, h1);
        fma2(acc[0][2], wa.x, h2); fma2(acc[0][3], wa.x, h3);
        fma2(acc[1][0], wa.y, h0); fma2(acc[1][1], wa.y, h1);
        fma2(acc[1][2], wa.y, h2); fma2(acc[1][3], wa.y, h3);
        fma2(acc[2][0], wb.x, h0); fma2(acc[2][1], wb.x, h1);
        fma2(acc[2][2], wb.x, h2); fma2(acc[2][3], wb.x, h3);
        fma2(acc[3][0], wb.y, h0); fma2(acc[3][1], wb.y, h1);
        fma2(acc[3][2], wb.y, h2); fma2(acc[3][3], wb.y, h3);
    }

    ulonglong2* dst = redu + (size_t)ksub * 512 + r;
    #pragma unroll
    for (int rp = 0; rp < 4; rp++)
        #pragma unroll
        for (int bh = 0; bh < 2; bh++)
            dst[(rp * 2 + bh) * 64] = make_ulonglong2(acc[rp][2 * bh],
                                                      acc[rp][2 * bh + 1]);
}

// ---------------------------------------------------------------------------
// Combined gate reduce: threads split over both layers; z -> zbuf(alias hsf).
// ---------------------------------------------------------------------------
template <bool DO1, bool DO2>
__device__ __forceinline__ void gate_reduce(
    const float* __restrict__ xg1p, const float* __restrict__ xg2p,
    const ulonglong2* redu1, const ulonglong2* redu2,
    float* zbuf1, float* zbuf2)
{
    const int t = threadIdx.x;
    const int layer = t >> 8;
    const int rr = (t >> 2) & 63;
    const int q = t & 3;
    if ((layer == 0 && !DO1) || (layer == 1 && !DO2)) return;

    const ulonglong2* redu = layer ? redu2 : redu1;
    const float* xg = layer ? xg2p : xg1p;
    float* zb = layer ? zbuf2 : zbuf1;

    const int rowg = rr >> 2, bg = (rr & 3) << 2;
    const int gate = rowg >> 2, jj = (rowg & 3) << 3;
    const int rowb = gate * HID + blockIdx.x * 32 + jj;

    #pragma unroll
    for (int si = 0; si < 2; si++) {
        int s = 2 * q + si;
        ulonglong2 sum = redu[s * 64 + rr];
        #pragma unroll
        for (int g = 1; g < 8; g++) {
            ulonglong2 v = redu[(size_t)g * 512 + s * 64 + rr];
            sum.x = add2(sum.x, v.x);
            sum.y = add2(sum.y, v.y);
        }
        int rp = s >> 1, bh = s & 1;
        int b0 = bg + 2 * bh;
        int jb = jj + 2 * rp;
        int rowp = rowb + 2 * rp;
        float2 x0 = __ldcs((const float2*)(xg + (size_t)b0 * G4H + rowp));
        float2 x1 = __ldcs((const float2*)(xg + (size_t)(b0 + 1) * G4H + rowp));
        float2 a0 = up2(sum.x), a1 = up2(sum.y);
        float2 z0 = {a0.x + x0.x, a0.y + x0.y};
        float2 z1 = {a1.x + x1.x, a1.y + x1.y};
        *(float2*)&zb[gate * 512 + b0 * 32 + jb] = z0;
        *(float2*)&zb[gate * 512 + (b0 + 1) * 32 + jb] = z1;
    }
}

// ---------------------------------------------------------------------------
// Cell update for both layers (c-state in registers).
// ---------------------------------------------------------------------------
template <bool DO1, bool DO2>
__device__ __forceinline__ void cell_update(
    const float* zbuf1, const float* zbuf2,
    float& c1r, float& c2r, bool last1, bool last2)
{
    const int tid = threadIdx.x;
    const int b = tid >> 5, jl = tid & 31;
    const size_t off = (size_t)b * HID + blockIdx.x * 32 + jl;
    if (DO1) {
        float zi = zbuf1[0 * 512 + b * 32 + jl];
        float zf = zbuf1[1 * 512 + b * 32 + jl];
        float zg = zbuf1[2 * 512 + b * 32 + jl];
        float zo = zbuf1[3 * 512 + b * 32 + jl];
        float cn = sigf(zf) * c1r + sigf(zi) * tanhf(zg);
        c1r = cn;
        g_g1h[off] = sigf(zo) * tanhf(cn);
        if (last1) g_c1[off] = cn;
    }
    if (DO2) {
        float zi = zbuf2[0 * 512 + b * 32 + jl];
        float zf = zbuf2[1 * 512 + b * 32 + jl];
        float zg = zbuf2[2 * 512 + b * 32 + jl];
        float zo = zbuf2[3 * 512 + b * 32 + jl];
        float cn = sigf(zf) * c2r + sigf(zi) * tanhf(zg);
        c2r = cn;
        g_g2h[off] = sigf(zo) * tanhf(cn);
        if (last2) g_c2[off] = cn;
    }
}

// ---------------------------------------------------------------------------
// Proj staging + main loop (all 4 ks groups write partials) + combined reduce.
// ---------------------------------------------------------------------------
__device__ __forceinline__ void stage_g(const float* __restrict__ gh,
                                        int kb, float* gpf) {
    const int tid = threadIdx.x;
    int bb = tid >> 7, k = tid & 127;
    int b0 = 4 * bb;
    float4 v;
    v.x = __ldcs(gh + (size_t)(b0 + 0) * HID + kb + k);
    v.y = __ldcs(gh + (size_t)(b0 + 1) * HID + kb + k);
    v.z = __ldcs(gh + (size_t)(b0 + 2) * HID + kb + k);
    v.w = __ldcs(gh + (size_t)(b0 + 3) * HID + kb + k);
    *(float4*)&gpf[k * HSTR + 4 * bb] = v;
}

__device__ __forceinline__ void proj_loop(
    const float* gpf, const float* __restrict__ Wtr,
    int p0, int kb, unsigned long long* predu)
{
    const int tid = threadIdx.x;
    const int ks = tid >> 7, r = tid & 127;
    const int rowg = r >> 2, bg = (r & 3) << 2;
    const int p4 = p0 + rowg * 4;
    const int kbeg = ks * 32;

    const ulonglong2* wp = (const ulonglong2*)(Wtr + (size_t)(kb + kbeg) * PROJ + p4);
    const float* hp = gpf + kbeg * HSTR + bg;

    unsigned long long acc[2][4];
    #pragma unroll
    for (int i = 0; i < 2; i++)
        #pragma unroll
        for (int j = 0; j < 4; j++) acc[i][j] = 0ull;

    #pragma unroll 8
    for (int k = 0; k < 32; k++) {
        ulonglong2 w = wp[(size_t)k * (PROJ / 4)];
        float4 h = *(const float4*)(hp + k * HSTR);
        unsigned long long h0 = pk2(h.x, h.x), h1 = pk2(h.y, h.y);
        unsigned long long h2 = pk2(h.z, h.z), h3 = pk2(h.w, h.w);
        fma2(acc[0][0], w.x, h0); fma2(acc[1][0], w.y, h0);
        fma2(acc[0][1], w.x, h1); fma2(acc[1][1], w.y, h1);
        fma2(acc[0][2], w.x, h2); fma2(acc[1][2], w.y, h2);
        fma2(acc[0][3], w.x, h3); fma2(acc[1][3], w.y, h3);
    }

    unsigned long long* dst = predu + (size_t)ks * 1152 + r * 9;
    #pragma unroll
    for (int rp = 0; rp < 2; rp++)
        #pragma unroll
        for (int bi = 0; bi < 4; bi++) dst[rp * 4 + bi] = acc[rp][bi];
}

template <bool DO1, bool DO2>
__device__ __forceinline__ void proj_reduce(
    float* __restrict__ hout1, float* __restrict__ hout2,
    const unsigned long long* predu1, const unsigned long long* predu2, int p0)
{
    const int t = threadIdx.x;
    const int layer = t >> 8;
    const int rr = (t >> 1) & 127;
    const int q = t & 1;
    if ((layer == 0 && !DO1) || (layer == 1 && !DO2)) return;

    const unsigned long long* predu = layer ? predu2 : predu1;
    float* hout = layer ? hout2 : hout1;
    const int rowg = rr >> 2, bg = (rr & 3) << 2;
    const int p4 = p0 + rowg * 4;

    #pragma unroll
    for (int bi = 0; bi < 4; bi++) {
        unsigned long long sum = predu[rr * 9 + q * 4 + bi];
        #pragma unroll
        for (int g = 1; g < 4; g++)
            sum = add2(sum, predu[(size_t)g * 1152 + rr * 9 + q * 4 + bi]);
        float2 v = up2(sum);
        float* o = hout + (size_t)(bg + bi) * PROJ + p4 + 2 * q;
        atomicAdd(o + 0, v.x);
        atomicAdd(o + 1, v.y);
    }
}

// ---------------------------------------------------------------------------
// Persistent recurrence with fused dual-layer phases:
//   prologue: G1(0) | P1(0)
//   loop t=0..254:  [G1(t+1) + G2(t)] |bar| [P1(t+1) + P2(t)] |bar|
//   tail: G2(255) | P2(255)
// ---------------------------------------------------------------------------
__global__ void __launch_bounds__(512, 1) recurrence_kernel() {
    extern __shared__ float smem[];
    float* hsf = smem;
    ulonglong2* redu1 = (ulonglong2*)(smem + 20480);
    ulonglong2* redu2 = (ulonglong2*)(smem + 36864);
    float* zbuf1 = smem;            // alias hsf (dead after gate loops)
    float* zbuf2 = smem + 2048;
    float* gpf1 = smem;
    float* gpf2 = smem + 2560;
    unsigned long long* predu1 = (unsigned long long*)(smem + 5120);
    unsigned long long* predu2 = (unsigned long long*)(smem + 14336);

    const int pt = blockIdx.x & 3;
    const int kc = blockIdx.x >> 2;
    const int p0 = pt * 128, kb = kc * 128;

    unsigned gen = g_genv;
    float c1r = 0.f, c2r = 0.f;

    // ---- prologue: G1(0) ----
    stage_h<512>(g_out1, nullptr, hsf);
    __syncthreads();
    gate_loop<512>(g_Wt1, hsf, redu1);
    __syncthreads();
    gate_reduce<true, false>(g_xg1, nullptr, redu1, redu2, zbuf1, zbuf2);
    __syncthreads();
    cell_update<true, false>(zbuf1, zbuf2, c1r, c2r, false, false);
    gsync(gen);
    // ---- P1(0) -> out1[1] ----
    stage_g(g_g1h, kb, gpf1);
    __syncthreads();
    proj_loop(gpf1, g_Wtr1, p0, kb, predu1);
    __syncthreads();
    proj_reduce<true, false>(g_out1 + (size_t)1 * (BATCH * PROJ), nullptr,
                             predu1, predu2, p0);
    gsync(gen);

    for (int t = 0; t < T_STEPS - 1; t++) {
        // fused gate phase: G1(t+1) + G2(t), one uninterrupted load stream
        stage_h<1024>(g_out1 + (size_t)(t + 1) * (BATCH * PROJ),
                      g_out2 + (size_t)t * (BATCH * PROJ), hsf);
        __syncthreads();
        gate_loop<512>(g_Wt1, hsf, redu1);
        gate_loop<1024>(g_Wt2, hsf, redu2);
        __syncthreads();
        gate_reduce<true, true>(g_xg1 + (size_t)(t + 1) * BATCH * G4H,
                                g_xg2 + (size_t)t * BATCH * G4H,
                                redu1, redu2, zbuf1, zbuf2);
        __syncthreads();
        cell_update<true, true>(zbuf1, zbuf2, c1r, c2r,
                                (t + 1 == T_STEPS - 1), false);
        gsync(gen);
        // fused proj phase: P1(t+1) + P2(t)
        stage_g(g_g1h, kb, gpf1);
        stage_g(g_g2h, kb, gpf2);
        __syncthreads();
        proj_loop(gpf1, g_Wtr1, p0, kb, predu1);
        proj_loop(gpf2, g_Wtr2, p0, kb, predu2);
        __syncthreads();
        proj_reduce<true, true>(g_out1 + (size_t)(t + 2) * (BATCH * PROJ),
                                g_out2 + (size_t)(t + 1) * (BATCH * PROJ),
                                predu1, predu2, p0);
        gsync(gen);
    }

    // ---- tail: G2(255) | P2(255) ----
    {
        int t = T_STEPS - 1;
        stage_h<1024>(g_out1 + (size_t)(t + 1) * (BATCH * PROJ),
                      g_out2 + (size_t)t * (BATCH * PROJ), hsf);
        __syncthreads();
        gate_loop<1024>(g_Wt2, hsf, redu2);
        __syncthreads();
        gate_reduce<false, true>(nullptr, g_xg2 + (size_t)t * BATCH * G4H,
                                 redu1, redu2, zbuf1, zbuf2);
        __syncthreads();
        cell_update<false, true>(zbuf1, zbuf2, c1r, c2r, false, true);
        gsync(gen);
        stage_g(g_g2h, kb, gpf2);
        __syncthreads();
        proj_loop(gpf2, g_Wtr2, p0, kb, predu2);
        __syncthreads();
        proj_reduce<false, true>(nullptr,
                                 g_out2 + (size_t)(t + 1) * (BATCH * PROJ),
                                 predu1, predu2, p0);
    }
}

// ---------------------------------------------------------------------------
// Heads: one warp per packed token
// ---------------------------------------------------------------------------
__global__ void __launch_bounds__(512) heads_kernel(
    const float* __restrict__ Wp, const float* __restrict__ bp,
    const float* __restrict__ Wa, const float* __restrict__ ba,
    float* __restrict__ out, int total) {
    const int t = blockIdx.x;
    const int w = threadIdx.x >> 5;
    const int lane = threadIdx.x & 31;
    if (w >= g_counts[t]) return;
    const int b = w;
    const int tok = g_offsets[t] + b;

    const float* o1 = g_out1 + (size_t)(t + 1) * (BATCH * PROJ) + (size_t)b * PROJ;
    const float* o2 = g_out2 + (size_t)(t + 1) * (BATCH * PROJ) + (size_t)b * PROJ;
    float v[16];
    #pragma unroll
    for (int i = 0; i < 16; i++) v[i] = o1[lane + 32 * i] + o2[lane + 32 * i];

    __shared__ float sp[16][20];
    __shared__ float sa[16][20];
    #pragma unroll
    for (int o = 0; o < 20; o++) {
        float s1 = 0.f, s2 = 0.f;
        #pragma unroll
        for (int i = 0; i < 16; i++) {
            float x = v[i];
            s1 = fmaf(x, Wp[o * PROJ + lane + 32 * i], s1);
            s2 = fmaf(x, Wa[o * PROJ + lane + 32 * i], s2);
        }
        #pragma unroll
        for (int off = 16; off; off >>= 1) {
            s1 += __shfl_xor_sync(0xffffffffu, s1, off);
            s2 += __shfl_xor_sync(0xffffffffu, s2, off);
        }
        if (lane == 0) { sp[w][o] = s1 + bp[o]; sa[w][o] = s2 + ba[o]; }
    }
    __syncwarp();
    if (lane == 0) {
        float m = -1e30f;
        #pragma unroll
        for (int o = 0; o < 20; o++) m = fmaxf(m, sp[w][o]);
        float e[20], sum = 0.f;
        #pragma unroll
        for (int o = 0; o < 20; o++) { e[o] = expf(sp[w][o] - m); sum += e[o]; }
        float inv = 1.f / sum;
        float* aa = out + (size_t)total * 20;
        #pragma unroll
        for (int o = 0; o < 20; o++) {
            out[(size_t)tok * 20 + o] = e[o] * inv;
            aa[(size_t)tok * 20 + o]  = sa[w][o];
        }
    }
}

// ---------------------------------------------------------------------------
// Final states: h1, c1, h2, c2
// ---------------------------------------------------------------------------
__global__ void finalize_kernel(float* __restrict__ out, int total) {
    const size_t base = (size_t)total * 40;
    const int nH = BATCH * PROJ;
    const int nC = BATCH * HID;
    int idx = blockIdx.x * blockDim.x + threadIdx.x;
    if (idx >= 2 * (nH + nC)) return;
    float v;
    if (idx < nH)                v = g_out1[(size_t)T_STEPS * nH + idx];
    else if (idx < nH + nC)      v = g_c1[idx - nH];
    else if (idx < 2 * nH + nC)  v = g_out2[(size_t)T_STEPS * nH + (idx - nH - nC)];
    else                         v = g_c2[idx - 2 * nH - nC];
    out[base + idx] = v;
}

// ---------------------------------------------------------------------------
// Host launch
// ---------------------------------------------------------------------------
extern "C" void kernel_launch(void* const* d_in, const int* in_sizes, int n_in,
                              void* d_out, int out_size) {
    const float* uncon  = (const float*)d_in[0];
    const float* con    = (const float*)d_in[1];
    const int*   lens   = (const int*)d_in[2];
    const float* W_ih1  = (const float*)d_in[3];
    const float* b1     = (const float*)d_in[4];
    const float* W_hh1  = (const float*)d_in[5];
    const float* W_hr1  = (const float*)d_in[6];
    const float* W_ih2  = (const float*)d_in[7];
    const float* b2     = (const float*)d_in[8];
    const float* W_hh2  = (const float*)d_in[9];
    const float* W_hr2  = (const float*)d_in[10];
    const float* W_pssm = (const float*)d_in[11];
    const float* b_pssm = (const float*)d_in[12];
    const float* W_aa   = (const float*)d_in[13];
    const float* b_aa   = (const float*)d_in[14];
    float* out = (float*)d_out;

    const int total = (out_size - 2 * (BATCH * PROJ + BATCH * HID)) / 40;

    float *p_xg1, *p_xg2;
    cudaGetSymbolAddress((void**)&p_xg1, g_xg1);
    cudaGetSymbolAddress((void**)&p_xg2, g_xg2);

    cudaFuncSetAttribute(recurrence_kernel,
                         cudaFuncAttributeMaxDynamicSharedMemorySize, SM_TOTAL_B);

    // 1: fused prep (transposes + zero + counts)
    prep_kernel<<<30721, 256>>>(W_hh1, W_ih2, W_hh2, W_hr1, W_hr2, lens);
    // 2,3: Phase A on tensor cores (3xTF32)
    sgemm_tf32<<<dim3(G4H / 128, (T_STEPS * BATCH) / 128), 256>>>(
        uncon, W_ih1, b1, p_xg1, F1, F1, F1, 0);
    sgemm_tf32<<<dim3(G4H / 128, (T_STEPS * BATCH) / 128), 256>>>(
        con, W_ih2, b2, p_xg2, F2CON, F2CON, 1280, 512);
    // 4: persistent recurrence
    recurrence_kernel<<<NBLK, 512, SM_TOTAL_B>>>();
    // 5,6: heads + final states
    heads_kernel<<<T_STEPS, 512>>>(W_pssm, b_pssm, W_aa, b_aa, out, total);
    finalize_kernel<<<(2 * (BATCH * PROJ + BATCH * HID) + 255) / 256, 256>>>(out, total);
}

// round 12
// speedup vs baseline: 1.5428x; 1.4545x over previous
#include <cuda_runtime.h>
#include <cuda_fp16.h>
#include <math.h>
#include <stdint.h>

// ---------------------------------------------------------------------------
// Problem constants
// ---------------------------------------------------------------------------
#define T_STEPS 256
#define BATCH   16
#define HID     4096          // H
#define PROJ    512           // P
#define G4H     16384         // 4*H
#define F1      532
#define F2CON   768           // con_x features (1280-512)
#define NBLK    128           // persistent grid size
#define HSTR    20            // padded smem row stride (floats) for h tiles

#define TSTR 136              // tf32 sgemm smem stride (floats)

// persistent-kernel dynamic smem (floats) — same layout as R11
#define SM_TOTAL_F 53248
#define SM_TOTAL_B (SM_TOTAL_F * 4)     // 212992

// ---------------------------------------------------------------------------
// Device scratch (static only — no cudaMalloc allowed)
// ---------------------------------------------------------------------------
__device__ float g_xg1[(size_t)T_STEPS * BATCH * G4H];   // 268 MB
__device__ float g_xg2[(size_t)T_STEPS * BATCH * G4H];   // 268 MB
__device__ __half g_Wt1h[(size_t)512 * G4H];             // W_hh1^T [k][row] fp16 (16 MB)
__device__ __half g_Wt2h[(size_t)1024 * G4H];            // [W_ih2[:,:512]; W_hh2]^T fp16 (32 MB)
__device__ float g_Wtr1[(size_t)HID * PROJ];             // W_hr1^T [k][p] fp32 (8 MB)
__device__ float g_Wtr2[(size_t)HID * PROJ];
__device__ float g_out1[(size_t)(T_STEPS + 1) * BATCH * PROJ];
__device__ float g_out2[(size_t)(T_STEPS + 1) * BATCH * PROJ];
__device__ float g_c1[BATCH * HID];
__device__ float g_c2[BATCH * HID];
__device__ float g_g1h[BATCH * HID];
__device__ float g_g2h[BATCH * HID];
__device__ int   g_counts[T_STEPS];
__device__ int   g_offsets[T_STEPS + 1];

__device__ volatile unsigned g_genv;   // monotonic across replays
__device__ unsigned g_arrive;          // self-resetting

// ---------------------------------------------------------------------------
// packed f32x2 helpers
// ---------------------------------------------------------------------------
__device__ __forceinline__ unsigned long long pk2(float x, float y) {
    unsigned long long d;
    asm("mov.b64 %0, {%1, %2};" : "=l"(d) : "f"(x), "f"(y));
    return d;
}
__device__ __forceinline__ void fma2(unsigned long long& a, unsigned long long b,
                                     unsigned long long c) {
    asm("fma.rn.f32x2 %0, %1, %2, %0;" : "+l"(a) : "l"(b), "l"(c));
}
__device__ __forceinline__ unsigned long long add2(unsigned long long a,
                                                   unsigned long long b) {
    unsigned long long d;
    asm("add.rn.f32x2 %0, %1, %2;" : "=l"(d) : "l"(a), "l"(b));
    return d;
}
__device__ __forceinline__ float2 up2(unsigned long long d) {
    float2 r;
    asm("mov.b64 {%0, %1}, %2;" : "=f"(r.x), "=f"(r.y) : "l"(d));
    return r;
}
__device__ __forceinline__ float sigf(float x) { return 1.f / (1.f + expf(-x)); }

// convert a packed half2 (as uint32) to an f32x2 ull (rows pair)
__device__ __forceinline__ unsigned long long h2w(uint32_t h) {
    float2 f = __half22float2(*(__half2*)&h);
    return pk2(f.x, f.y);
}

// ---------------------------------------------------------------------------
// tf32 helpers (3xTF32 split GEMM)
// ---------------------------------------------------------------------------
__device__ __forceinline__ uint32_t f2tf(float x) {
    uint32_t r;
    asm("cvt.rna.tf32.f32 %0, %1;" : "=r"(r) : "f"(x));
    return r;
}
__device__ __forceinline__ void mma_tf32(float c[4], const uint32_t a[4],
                                         const uint32_t b[2]) {
    asm volatile(
        "mma.sync.aligned.m16n8k8.row.col.f32.tf32.tf32.f32 "
        "{%0,%1,%2,%3}, {%4,%5,%6,%7}, {%8,%9}, {%0,%1,%2,%3};\n"
        : "+f"(c[0]), "+f"(c[1]), "+f"(c[2]), "+f"(c[3])
        : "r"(a[0]), "r"(a[1]), "r"(a[2]), "r"(a[3]), "r"(b[0]), "r"(b[1]));
}

// ---------------------------------------------------------------------------
// grid-wide barrier
// ---------------------------------------------------------------------------
__device__ __forceinline__ void gsync(unsigned& gen) {
    __syncthreads();
    if (threadIdx.x == 0) {
        unsigned next = gen + 1;
        __threadfence();
        if (atomicAdd(&g_arrive, 1u) == (unsigned)(NBLK - 1)) {
            g_arrive = 0u;
            __threadfence();
            g_genv = next;
        } else {
            while (g_genv != next) {}
            __threadfence();
        }
        gen = next;
    }
    __syncthreads();
}

// ---------------------------------------------------------------------------
// Fused prep: weight transposes (gate->fp16, proj->fp32) + zero + counts.
// blocks [0,24576): gate transposes (half out); [24576,28672): proj (float);
// 28672: counts; (28672,30721): zero.
// ---------------------------------------------------------------------------
__global__ void prep_kernel(const float* __restrict__ W_hh1,
                            const float* __restrict__ W_ih2,
                            const float* __restrict__ W_hh2,
                            const float* __restrict__ W_hr1,
                            const float* __restrict__ W_hr2,
                            const int* __restrict__ lens) {
    int bid = blockIdx.x;
    int tid = threadIdx.x;
    if (bid < 24576) {
        __shared__ float tile[32][33];
        const float* in;
        __half* out;
        int ldin, tix;
        if (bid < 8192)       { in = W_hh1; out = g_Wt1h; ldin = 512;  tix = bid; }
        else if (bid < 16384) { in = W_ih2; out = g_Wt2h; ldin = 1280; tix = bid - 8192; }
        else                  { in = W_hh2; out = g_Wt2h + (size_t)512 * G4H;
                                                           ldin = 512;  tix = bid - 16384; }
        const int rows = G4H;
        int nbx = rows >> 5;
        int bx = tix % nbx, by = tix / nbx;
        int j0 = bx * 32, k0 = by * 32;
        int tx = tid & 31, ty = tid >> 5;
        #pragma unroll
        for (int i = 0; i < 32; i += 8) {
            int j = j0 + ty + i, k = k0 + tx;
            tile[ty + i][tx] = in[(size_t)j * ldin + k];
        }
        __syncthreads();
        #pragma unroll
        for (int i = 0; i < 32; i += 8) {
            int k = k0 + ty + i, j = j0 + tx;
            out[(size_t)k * rows + j] = __float2half(tile[tx][ty + i]);
        }
    } else if (bid < 28672) {
        __shared__ float tile[32][33];
        const float* in;
        float* out;
        int tix;
        if (bid < 26624) { in = W_hr1; out = g_Wtr1; tix = bid - 24576; }
        else             { in = W_hr2; out = g_Wtr2; tix = bid - 26624; }
        const int rows = 512, ldin = HID;
        int nbx = rows >> 5;
        int bx = tix % nbx, by = tix / nbx;
        int j0 = bx * 32, k0 = by * 32;
        int tx = tid & 31, ty = tid >> 5;
        #pragma unroll
        for (int i = 0; i < 32; i += 8) {
            int j = j0 + ty + i, k = k0 + tx;
            tile[ty + i][tx] = in[(size_t)j * ldin + k];
        }
        __syncthreads();
        #pragma unroll
        for (int i = 0; i < 32; i += 8) {
            int k = k0 + ty + i, j = j0 + tx;
            out[(size_t)k * rows + j] = tile[tx][ty + i];
        }
    } else if (bid == 28672) {
        int t = tid;
        int c = 0;
        #pragma unroll
        for (int b = 0; b < BATCH; b++) c += (lens[b] > t) ? 1 : 0;
        g_counts[t] = c;
        __syncthreads();
        if (t == 0) {
            int s = 0;
            for (int i = 0; i < T_STEPS; i++) { g_offsets[i] = s; s += g_counts[i]; }
            g_offsets[T_STEPS] = s;
        }
    } else {
        const size_t n1 = (size_t)(T_STEPS + 1) * BATCH * PROJ;
        const size_t nc = (size_t)BATCH * HID;
        const size_t tot = 2 * n1 + 2 * nc;
        size_t base = (size_t)(bid - 28673) * 256 + tid;
        for (size_t i = base; i < tot; i += (size_t)2048 * 256) {
            if (i < n1)               g_out1[i] = 0.f;
            else if (i < 2 * n1)      g_out2[i - n1] = 0.f;
            else if (i < 2 * n1 + nc) g_c1[i - 2 * n1] = 0.f;
            else                      g_c2[i - 2 * n1 - nc] = 0.f;
        }
    }
}

// ---------------------------------------------------------------------------
// Phase A GEMM on tensor cores: 3xTF32 (fp32-grade accuracy).
// ---------------------------------------------------------------------------
__global__ void __launch_bounds__(256)
sgemm_tf32(const float* __restrict__ A, const float* __restrict__ B,
           const float* __restrict__ bias, float* __restrict__ C,
           int K, int lda, int ldb, int boff) {
    __shared__ float Ah[16 * TSTR], Al[16 * TSTR];
    __shared__ float Bh[16 * TSTR], Bl[16 * TSTR];

    const int tid = threadIdx.x;
    const int m0 = blockIdx.y * 128, n0 = blockIdx.x * 128;
    const int warp = tid >> 5, lane = tid & 31;
    const int wm = (warp >> 2) * 64;
    const int wn = (warp & 3) * 32;
    const int g  = lane >> 2;
    const int tk = lane & 3;

    float c[4][4][4];
    #pragma unroll
    for (int mt = 0; mt < 4; mt++)
        #pragma unroll
        for (int nt = 0; nt < 4; nt++)
            #pragma unroll
            for (int i = 0; i < 4; i++) c[mt][nt][i] = 0.f;

    const int rr = tid >> 4;
    const int cc = tid & 15;

    for (int k0 = 0; k0 < K; k0 += 16) {
        __syncthreads();
        const bool kv = (k0 + cc) < K;
        #pragma unroll
        for (int i = 0; i < 8; i++) {
            int r = rr + i * 16;
            float av = kv ? A[(size_t)(m0 + r) * lda + k0 + cc] : 0.f;
            float bv = kv ? B[(size_t)(n0 + r) * ldb + boff + k0 + cc] : 0.f;
            uint32_t ah = f2tf(av);
            uint32_t bh = f2tf(bv);
            Ah[cc * TSTR + r] = __uint_as_float(ah);
            Al[cc * TSTR + r] = __uint_as_float(f2tf(av - __uint_as_float(ah)));
            Bh[cc * TSTR + r] = __uint_as_float(bh);
            Bl[cc * TSTR + r] = __uint_as_float(f2tf(bv - __uint_as_float(bh)));
        }
        __syncthreads();

        #pragma unroll
        for (int ks = 0; ks < 16; ks += 8) {
            const int kk = ks + tk;
            uint32_t ahf[4][4], alf[4][4], bhf[4][2], blf[4][2];
            #pragma unroll
            for (int mt = 0; mt < 4; mt++) {
                int rb = wm + mt * 16 + g;
                ahf[mt][0] = __float_as_uint(Ah[kk * TSTR + rb]);
                ahf[mt][1] = __float_as_uint(Ah[kk * TSTR + rb + 8]);
                ahf[mt][2] = __float_as_uint(Ah[(kk + 4) * TSTR + rb]);
                ahf[mt][3] = __float_as_uint(Ah[(kk + 4) * TSTR + rb + 8]);
                alf[mt][0] = __float_as_uint(Al[kk * TSTR + rb]);
                alf[mt][1] = __float_as_uint(Al[kk * TSTR + rb + 8]);
                alf[mt][2] = __float_as_uint(Al[(kk + 4) * TSTR + rb]);
                alf[mt][3] = __float_as_uint(Al[(kk + 4) * TSTR + rb + 8]);
            }
            #pragma unroll
            for (int nt = 0; nt < 4; nt++) {
                int nb = wn + nt * 8 + g;
                bhf[nt][0] = __float_as_uint(Bh[kk * TSTR + nb]);
                bhf[nt][1] = __float_as_uint(Bh[(kk + 4) * TSTR + nb]);
                blf[nt][0] = __float_as_uint(Bl[kk * TSTR + nb]);
                blf[nt][1] = __float_as_uint(Bl[(kk + 4) * TSTR + nb]);
            }
            #pragma unroll
            for (int mt = 0; mt < 4; mt++)
                #pragma unroll
                for (int nt = 0; nt < 4; nt++) {
                    mma_tf32(c[mt][nt], ahf[mt], bhf[nt]);
                    mma_tf32(c[mt][nt], ahf[mt], blf[nt]);
                    mma_tf32(c[mt][nt], alf[mt], bhf[nt]);
                }
        }
    }

    #pragma unroll
    for (int nt = 0; nt < 4; nt++) {
        int col = n0 + wn + nt * 8 + 2 * tk;
        float b0 = bias[col], b1 = bias[col + 1];
        #pragma unroll
        for (int mt = 0; mt < 4; mt++) {
            int row0 = m0 + wm + mt * 16 + g;
            float2 v0 = {c[mt][nt][0] + b0, c[mt][nt][1] + b1};
            float2 v1 = {c[mt][nt][2] + b0, c[mt][nt][3] + b1};
            __stcs((float2*)(C + (size_t)row0 * G4H + col), v0);
            __stcs((float2*)(C + (size_t)(row0 + 8) * G4H + col), v1);
        }
    }
}

// ---------------------------------------------------------------------------
// Stage h into hsf[k*HSTR + b].
// ---------------------------------------------------------------------------
template <int KROWS>
__device__ __forceinline__ void stage_h(const float* __restrict__ src1,
                                        const float* __restrict__ src2,
                                        float* hsf) {
    const int tid = threadIdx.x;
    for (int idx = tid; idx < 4 * KROWS; idx += 512) {
        int bb, k;
        if (KROWS == 512) { bb = idx >> 9;  k = idx & 511;  }
        else              { bb = idx >> 10; k = idx & 1023; }
        int b0 = 4 * bb;
        const float* s = (KROWS == 512 || k < 512) ? (src1 + k) : (src2 + (k - 512));
        float4 v;
        v.x = s[(b0 + 0) * PROJ];
        v.y = s[(b0 + 1) * PROJ];
        v.z = s[(b0 + 2) * PROJ];
        v.w = s[(b0 + 3) * PROJ];
        *(float4*)&hsf[k * HSTR + 4 * bb] = v;
    }
}

// ---------------------------------------------------------------------------
// Gate main loop, fp16 weights: 1 LDG.128 per k yields 8 row-weights.
// 8-way K split, micro-tile 8 rows x 4 batches, partials to smem.
// ---------------------------------------------------------------------------
template <int KTOT>
__device__ __forceinline__ void gate_loop(const __half* __restrict__ Wt,
                                          const float* hsf, ulonglong2* redu) {
    const int tid = threadIdx.x;
    const int ksub = tid >> 6;            // 0..7
    const int r    = tid & 63;            // 0..63
    const int rowg = r >> 2;              // 0..15
    const int bg   = (r & 3) << 2;        // 0,4,8,12
    const int gate = rowg >> 2;           // 0..3
    const int j0   = blockIdx.x * 32;
    const int jj   = (rowg & 3) << 3;     // 0,8,16,24
    const int row8 = gate * HID + j0 + jj;
    const int kh   = KTOT / 8;
    const int kbeg = ksub * kh;

    const uint4* wp = (const uint4*)(Wt + (size_t)kbeg * G4H + row8);
    const float* hp = hsf + (size_t)kbeg * HSTR + bg;

    unsigned long long acc[4][4];
    #pragma unroll
    for (int i = 0; i < 4; i++)
        #pragma unroll
        for (int j = 0; j < 4; j++) acc[i][j] = 0ull;

    #pragma unroll 8
    for (int k = 0; k < kh; k++) {
        uint4 wv = wp[(size_t)k * (G4H / 8)];        // 8 fp16 weights (rows 0..7)
        unsigned long long w01 = h2w(wv.x);
        unsigned long long w23 = h2w(wv.y);
        unsigned long long w45 = h2w(wv.z);
        unsigned long long w67 = h2w(wv.w);
        float4 h = *(const float4*)(hp + k * HSTR);
        unsigned long long h0 = pk2(h.x, h.x), h1 = pk2(h.y, h.y);
        unsigned long long h2 = pk2(h.z, h.z), h3 = pk2(h.w, h.w);
        fma2(acc[0][0], w01, h0); fma2(acc[0][1], w01, h1);
        fma2(acc[0][2], w01, h2); fma2(acc[0][3], w01, h3);
        fma2(acc[1][0], w23, h0); fma2(acc[1][1], w23, h1);
        fma2(acc[1][2], w23, h2); fma2(acc[1][3], w23, h3);
        fma2(acc[2][0], w45, h0); fma2(acc[2][1], w45, h1);
        fma2(acc[2][2], w45, h2); fma2(acc[2][3], w45, h3);
        fma2(acc[3][0], w67, h0); fma2(acc[3][1], w67, h1);
        fma2(acc[3][2], w67, h2); fma2(acc[3][3], w67, h3);
    }

    ulonglong2* dst = redu + (size_t)ksub * 512 + r;
    #pragma unroll
    for (int rp = 0; rp < 4; rp++)
        #pragma unroll
        for (int bh = 0; bh < 2; bh++)
            dst[(rp * 2 + bh) * 64] = make_ulonglong2(acc[rp][2 * bh],
                                                      acc[rp][2 * bh + 1]);
}

// ---------------------------------------------------------------------------
// Combined gate reduce: threads split over both layers; z -> zbuf(alias hsf).
// ---------------------------------------------------------------------------
template <bool DO1, bool DO2>
__device__ __forceinline__ void gate_reduce(
    const float* __restrict__ xg1p, const float* __restrict__ xg2p,
    const ulonglong2* redu1, const ulonglong2* redu2,
    float* zbuf1, float* zbuf2)
{
    const int t = threadIdx.x;
    const int layer = t >> 8;
    const int rr = (t >> 2) & 63;
    const int q = t & 3;
    if ((layer == 0 && !DO1) || (layer == 1 && !DO2)) return;

    const ulonglong2* redu = layer ? redu2 : redu1;
    const float* xg = layer ? xg2p : xg1p;
    float* zb = layer ? zbuf2 : zbuf1;

    const int rowg = rr >> 2, bg = (rr & 3) << 2;
    const int gate = rowg >> 2, jj = (rowg & 3) << 3;
    const int rowb = gate * HID + blockIdx.x * 32 + jj;

    #pragma unroll
    for (int si = 0; si < 2; si++) {
        int s = 2 * q + si;
        ulonglong2 sum = redu[s * 64 + rr];
        #pragma unroll
        for (int g = 1; g < 8; g++) {
            ulonglong2 v = redu[(size_t)g * 512 + s * 64 + rr];
            sum.x = add2(sum.x, v.x);
            sum.y = add2(sum.y, v.y);
        }
        int rp = s >> 1, bh = s & 1;
        int b0 = bg + 2 * bh;
        int jb = jj + 2 * rp;
        int rowp = rowb + 2 * rp;
        float2 x0 = __ldcs((const float2*)(xg + (size_t)b0 * G4H + rowp));
        float2 x1 = __ldcs((const float2*)(xg + (size_t)(b0 + 1) * G4H + rowp));
        float2 a0 = up2(sum.x), a1 = up2(sum.y);
        float2 z0 = {a0.x + x0.x, a0.y + x0.y};
        float2 z1 = {a1.x + x1.x, a1.y + x1.y};
        *(float2*)&zb[gate * 512 + b0 * 32 + jb] = z0;
        *(float2*)&zb[gate * 512 + (b0 + 1) * 32 + jb] = z1;
    }
}

// ---------------------------------------------------------------------------
// Cell update for both layers (c-state in registers).
// ---------------------------------------------------------------------------
template <bool DO1, bool DO2>
__device__ __forceinline__ void cell_update(
    const float* zbuf1, const float* zbuf2,
    float& c1r, float& c2r, bool last1, bool last2)
{
    const int tid = threadIdx.x;
    const int b = tid >> 5, jl = tid & 31;
    const size_t off = (size_t)b * HID + blockIdx.x * 32 + jl;
    if (DO1) {
        float zi = zbuf1[0 * 512 + b * 32 + jl];
        float zf = zbuf1[1 * 512 + b * 32 + jl];
        float zg = zbuf1[2 * 512 + b * 32 + jl];
        float zo = zbuf1[3 * 512 + b * 32 + jl];
        float cn = sigf(zf) * c1r + sigf(zi) * tanhf(zg);
        c1r = cn;
        g_g1h[off] = sigf(zo) * tanhf(cn);
        if (last1) g_c1[off] = cn;
    }
    if (DO2) {
        float zi = zbuf2[0 * 512 + b * 32 + jl];
        float zf = zbuf2[1 * 512 + b * 32 + jl];
        float zg = zbuf2[2 * 512 + b * 32 + jl];
        float zo = zbuf2[3 * 512 + b * 32 + jl];
        float cn = sigf(zf) * c2r + sigf(zi) * tanhf(zg);
        c2r = cn;
        g_g2h[off] = sigf(zo) * tanhf(cn);
        if (last2) g_c2[off] = cn;
    }
}

// ---------------------------------------------------------------------------
// Proj staging + main loop + combined reduce (fp32 weights — exact proj).
// ---------------------------------------------------------------------------
__device__ __forceinline__ void stage_g(const float* __restrict__ gh,
                                        int kb, float* gpf) {
    const int tid = threadIdx.x;
    int bb = tid >> 7, k = tid & 127;
    int b0 = 4 * bb;
    float4 v;
    v.x = __ldcs(gh + (size_t)(b0 + 0) * HID + kb + k);
    v.y = __ldcs(gh + (size_t)(b0 + 1) * HID + kb + k);
    v.z = __ldcs(gh + (size_t)(b0 + 2) * HID + kb + k);
    v.w = __ldcs(gh + (size_t)(b0 + 3) * HID + kb + k);
    *(float4*)&gpf[k * HSTR + 4 * bb] = v;
}

__device__ __forceinline__ void proj_loop(
    const float* gpf, const float* __restrict__ Wtr,
    int p0, int kb, unsigned long long* predu)
{
    const int tid = threadIdx.x;
    const int ks = tid >> 7, r = tid & 127;
    const int rowg = r >> 2, bg = (r & 3) << 2;
    const int p4 = p0 + rowg * 4;
    const int kbeg = ks * 32;

    const ulonglong2* wp = (const ulonglong2*)(Wtr + (size_t)(kb + kbeg) * PROJ + p4);
    const float* hp = gpf + kbeg * HSTR + bg;

    unsigned long long acc[2][4];
    #pragma unroll
    for (int i = 0; i < 2; i++)
        #pragma unroll
        for (int j = 0; j < 4; j++) acc[i][j] = 0ull;

    #pragma unroll 8
    for (int k = 0; k < 32; k++) {
        ulonglong2 w = wp[(size_t)k * (PROJ / 4)];
        float4 h = *(const float4*)(hp + k * HSTR);
        unsigned long long h0 = pk2(h.x, h.x), h1 = pk2(h.y, h.y);
        unsigned long long h2 = pk2(h.z, h.z), h3 = pk2(h.w, h.w);
        fma2(acc[0][0], w.x, h0); fma2(acc[1][0], w.y, h0);
        fma2(acc[0][1], w.x, h1); fma2(acc[1][1], w.y, h1);
        fma2(acc[0][2], w.x, h2); fma2(acc[1][2], w.y, h2);
        fma2(acc[0][3], w.x, h3); fma2(acc[1][3], w.y, h3);
    }

    unsigned long long* dst = predu + (size_t)ks * 1152 + r * 9;
    #pragma unroll
    for (int rp = 0; rp < 2; rp++)
        #pragma unroll
        for (int bi = 0; bi < 4; bi++) dst[rp * 4 + bi] = acc[rp][bi];
}

template <bool DO1, bool DO2>
__device__ __forceinline__ void proj_reduce(
    float* __restrict__ hout1, float* __restrict__ hout2,
    const unsigned long long* predu1, const unsigned long long* predu2, int p0)
{
    const int t = threadIdx.x;
    const int layer = t >> 8;
    const int rr = (t >> 1) & 127;
    const int q = t & 1;
    if ((layer == 0 && !DO1) || (layer == 1 && !DO2)) return;

    const unsigned long long* predu = layer ? predu2 : predu1;
    float* hout = layer ? hout2 : hout1;
    const int rowg = rr >> 2, bg = (rr & 3) << 2;
    const int p4 = p0 + rowg * 4;

    #pragma unroll
    for (int bi = 0; bi < 4; bi++) {
        unsigned long long sum = predu[rr * 9 + q * 4 + bi];
        #pragma unroll
        for (int g = 1; g < 4; g++)
            sum = add2(sum, predu[(size_t)g * 1152 + rr * 9 + q * 4 + bi]);
        float2 v = up2(sum);
        float* o = hout + (size_t)(bg + bi) * PROJ + p4 + 2 * q;
        atomicAdd(o + 0, v.x);
        atomicAdd(o + 1, v.y);
    }
}

// ---------------------------------------------------------------------------
// Persistent recurrence with fused dual-layer phases.
// ---------------------------------------------------------------------------
__global__ void __launch_bounds__(512, 1) recurrence_kernel() {
    extern __shared__ float smem[];
    float* hsf = smem;
    ulonglong2* redu1 = (ulonglong2*)(smem + 20480);
    ulonglong2* redu2 = (ulonglong2*)(smem + 36864);
    float* zbuf1 = smem;            // alias hsf (dead after gate loops)
    float* zbuf2 = smem + 2048;
    float* gpf1 = smem;
    float* gpf2 = smem + 2560;
    unsigned long long* predu1 = (unsigned long long*)(smem + 5120);
    unsigned long long* predu2 = (unsigned long long*)(smem + 14336);

    const int pt = blockIdx.x & 3;
    const int kc = blockIdx.x >> 2;
    const int p0 = pt * 128, kb = kc * 128;

    unsigned gen = g_genv;
    float c1r = 0.f, c2r = 0.f;

    // ---- prologue: G1(0) ----
    stage_h<512>(g_out1, nullptr, hsf);
    __syncthreads();
    gate_loop<512>(g_Wt1h, hsf, redu1);
    __syncthreads();
    gate_reduce<true, false>(g_xg1, nullptr, redu1, redu2, zbuf1, zbuf2);
    __syncthreads();
    cell_update<true, false>(zbuf1, zbuf2, c1r, c2r, false, false);
    gsync(gen);
    // ---- P1(0) -> out1[1] ----
    stage_g(g_g1h, kb, gpf1);
    __syncthreads();
    proj_loop(gpf1, g_Wtr1, p0, kb, predu1);
    __syncthreads();
    proj_reduce<true, false>(g_out1 + (size_t)1 * (BATCH * PROJ), nullptr,
                             predu1, predu2, p0);
    gsync(gen);

    for (int t = 0; t < T_STEPS - 1; t++) {
        stage_h<1024>(g_out1 + (size_t)(t + 1) * (BATCH * PROJ),
                      g_out2 + (size_t)t * (BATCH * PROJ), hsf);
        __syncthreads();
        gate_loop<512>(g_Wt1h, hsf, redu1);
        gate_loop<1024>(g_Wt2h, hsf, redu2);
        __syncthreads();
        gate_reduce<true, true>(g_xg1 + (size_t)(t + 1) * BATCH * G4H,
                                g_xg2 + (size_t)t * BATCH * G4H,
                                redu1, redu2, zbuf1, zbuf2);
        __syncthreads();
        cell_update<true, true>(zbuf1, zbuf2, c1r, c2r,
                                (t + 1 == T_STEPS - 1), false);
        gsync(gen);
        stage_g(g_g1h, kb, gpf1);
        stage_g(g_g2h, kb, gpf2);
        __syncthreads();
        proj_loop(gpf1, g_Wtr1, p0, kb, predu1);
        proj_loop(gpf2, g_Wtr2, p0, kb, predu2);
        __syncthreads();
        proj_reduce<true, true>(g_out1 + (size_t)(t + 2) * (BATCH * PROJ),
                                g_out2 + (size_t)(t + 1) * (BATCH * PROJ),
                                predu1, predu2, p0);
        gsync(gen);
    }

    // ---- tail: G2(255) | P2(255) ----
    {
        int t = T_STEPS - 1;
        stage_h<1024>(g_out1 + (size_t)(t + 1) * (BATCH * PROJ),
                      g_out2 + (size_t)t * (BATCH * PROJ), hsf);
        __syncthreads();
        gate_loop<1024>(g_Wt2h, hsf, redu2);
        __syncthreads();
        gate_reduce<false, true>(nullptr, g_xg2 + (size_t)t * BATCH * G4H,
                                 redu1, redu2, zbuf1, zbuf2);
        __syncthreads();
        cell_update<false, true>(zbuf1, zbuf2, c1r, c2r, false, true);
        gsync(gen);
        stage_g(g_g2h, kb, gpf2);
        __syncthreads();
        proj_loop(gpf2, g_Wtr2, p0, kb, predu2);
        __syncthreads();
        proj_reduce<false, true>(nullptr,
                                 g_out2 + (size_t)(t + 1) * (BATCH * PROJ),
                                 predu1, predu2, p0);
    }
}

// ---------------------------------------------------------------------------
// Heads: one warp per packed token
// ---------------------------------------------------------------------------
__global__ void __launch_bounds__(512) heads_kernel(
    const float* __restrict__ Wp, const float* __restrict__ bp,
    const float* __restrict__ Wa, const float* __restrict__ ba,
    float* __restrict__ out, int total) {
    const int t = blockIdx.x;
    const int w = threadIdx.x >> 5;
    const int lane = threadIdx.x & 31;
    if (w >= g_counts[t]) return;
    const int b = w;
    const int tok = g_offsets[t] + b;

    const float* o1 = g_out1 + (size_t)(t + 1) * (BATCH * PROJ) + (size_t)b * PROJ;
    const float* o2 = g_out2 + (size_t)(t + 1) * (BATCH * PROJ) + (size_t)b * PROJ;
    float v[16];
    #pragma unroll
    for (int i = 0; i < 16; i++) v[i] = o1[lane + 32 * i] + o2[lane + 32 * i];

    __shared__ float sp[16][20];
    __shared__ float sa[16][20];
    #pragma unroll
    for (int o = 0; o < 20; o++) {
        float s1 = 0.f, s2 = 0.f;
        #pragma unroll
        for (int i = 0; i < 16; i++) {
            float x = v[i];
            s1 = fmaf(x, Wp[o * PROJ + lane + 32 * i], s1);
            s2 = fmaf(x, Wa[o * PROJ + lane + 32 * i], s2);
        }
        #pragma unroll
        for (int off = 16; off; off >>= 1) {
            s1 += __shfl_xor_sync(0xffffffffu, s1, off);
            s2 += __shfl_xor_sync(0xffffffffu, s2, off);
        }
        if (lane == 0) { sp[w][o] = s1 + bp[o]; sa[w][o] = s2 + ba[o]; }
    }
    __syncwarp();
    if (lane == 0) {
        float m = -1e30f;
        #pragma unroll
        for (int o = 0; o < 20; o++) m = fmaxf(m, sp[w][o]);
        float e[20], sum = 0.f;
        #pragma unroll
        for (int o = 0; o < 20; o++) { e[o] = expf(sp[w][o] - m); sum += e[o]; }
        float inv = 1.f / sum;
        float* aa = out + (size_t)total * 20;
        #pragma unroll
        for (int o = 0; o < 20; o++) {
            out[(size_t)tok * 20 + o] = e[o] * inv;
            aa[(size_t)tok * 20 + o]  = sa[w][o];
        }
    }
}

// ---------------------------------------------------------------------------
// Final states: h1, c1, h2, c2
// ---------------------------------------------------------------------------
__global__ void finalize_kernel(float* __restrict__ out, int total) {
    const size_t base = (size_t)total * 40;
    const int nH = BATCH * PROJ;
    const int nC = BATCH * HID;
    int idx = blockIdx.x * blockDim.x + threadIdx.x;
    if (idx >= 2 * (nH + nC)) return;
    float v;
    if (idx < nH)                v = g_out1[(size_t)T_STEPS * nH + idx];
    else if (idx < nH + nC)      v = g_c1[idx - nH];
    else if (idx < 2 * nH + nC)  v = g_out2[(size_t)T_STEPS * nH + (idx - nH - nC)];
    else                         v = g_c2[idx - 2 * nH - nC];
    out[base + idx] = v;
}

// ---------------------------------------------------------------------------
// Host launch
// ---------------------------------------------------------------------------
extern "C" void kernel_launch(void* const* d_in, const int* in_sizes, int n_in,
                              void* d_out, int out_size) {
    const float* uncon  = (const float*)d_in[0];
    const float* con    = (const float*)d_in[1];
    const int*   lens   = (const int*)d_in[2];
    const float* W_ih1  = (const float*)d_in[3];
    const float* b1     = (const float*)d_in[4];
    const float* W_hh1  = (const float*)d_in[5];
    const float* W_hr1  = (const float*)d_in[6];
    const float* W_ih2  = (const float*)d_in[7];
    const float* b2     = (const float*)d_in[8];
    const float* W_hh2  = (const float*)d_in[9];
    const float* W_hr2  = (const float*)d_in[10];
    const float* W_pssm = (const float*)d_in[11];
    const float* b_pssm = (const float*)d_in[12];
    const float* W_aa   = (const float*)d_in[13];
    const float* b_aa   = (const float*)d_in[14];
    float* out = (float*)d_out;

    const int total = (out_size - 2 * (BATCH * PROJ + BATCH * HID)) / 40;

    float *p_xg1, *p_xg2;
    cudaGetSymbolAddress((void**)&p_xg1, g_xg1);
    cudaGetSymbolAddress((void**)&p_xg2, g_xg2);

    cudaFuncSetAttribute(recurrence_kernel,
                         cudaFuncAttributeMaxDynamicSharedMemorySize, SM_TOTAL_B);

    // 1: fused prep (transposes [gate->fp16] + zero + counts)
    prep_kernel<<<30721, 256>>>(W_hh1, W_ih2, W_hh2, W_hr1, W_hr2, lens);
    // 2,3: Phase A on tensor cores (3xTF32)
    sgemm_tf32<<<dim3(G4H / 128, (T_STEPS * BATCH) / 128), 256>>>(
        uncon, W_ih1, b1, p_xg1, F1, F1, F1, 0);
    sgemm_tf32<<<dim3(G4H / 128, (T_STEPS * BATCH) / 128), 256>>>(
        con, W_ih2, b2, p_xg2, F2CON, F2CON, 1280, 512);
    // 4: persistent recurrence (fp16 gate weights, L2-resident)
    recurrence_kernel<<<NBLK, 512, SM_TOTAL_B>>>();
    // 5,6: heads + final states
    heads_kernel<<<T_STEPS, 512>>>(W_pssm, b_pssm, W_aa, b_aa, out, total);
    finalize_kernel<<<(2 * (BATCH * PROJ + BATCH * HID) + 255) / 256, 256>>>(out, total);
}

// round 13
// speedup vs baseline: 2.2914x; 1.4852x over previous
#include <cuda_runtime.h>
#include <cuda_fp16.h>
#include <math.h>
#include <stdint.h>

// ---------------------------------------------------------------------------
// Problem constants
// ---------------------------------------------------------------------------
#define T_STEPS 256
#define BATCH   16
#define HID     4096          // H
#define PROJ    512           // P
#define G4H     16384         // 4*H
#define F1      532
#define F2CON   768           // con_x features (1280-512)
#define NBLK    128           // persistent grid size
#define HSTR    20            // padded smem row stride (floats) for proj h tiles

#define TSTR 136              // tf32 sgemm smem stride (floats)

// persistent-kernel dynamic smem (floats):
//  gate phase: af (uint32) [0, 8192) | zbuf1 [8192,10240) | zbuf2 [10240,12288)
//  proj phase: gpf1 [0,2560) | gpf2 [2560,5120) | predu1 [5120,14336) | predu2 [14336,23552)
#define SM_TOTAL_F 23552
#define SM_TOTAL_B (SM_TOTAL_F * 4)     // 94208

// ---------------------------------------------------------------------------
// Device scratch (static only — no cudaMalloc allowed)
// ---------------------------------------------------------------------------
__device__ float g_xg1[(size_t)T_STEPS * BATCH * G4H];   // 268 MB
__device__ float g_xg2[(size_t)T_STEPS * BATCH * G4H];   // 268 MB
// gate weights packed in m16n8k16 B-fragment order (fp16):
// pb[nt][c][lane] = uint2{ half2(W[n][k0],W[n][k0+1]), half2(W[n][k0+8],W[n][k0+9]) }
//   n = nt*8 + lane/4, k0 = 16c + 2*(lane%4)
__device__ uint2 g_pb1[(size_t)2048 * 32 * 32];          // 16 MB (L1: K=512)
__device__ uint2 g_pb2[(size_t)2048 * 64 * 32];          // 32 MB (L2: K=1024)
__device__ float g_Wtr1[(size_t)HID * PROJ];             // W_hr1^T [k][p] fp32 (8 MB)
__device__ float g_Wtr2[(size_t)HID * PROJ];
__device__ float g_out1[(size_t)(T_STEPS + 1) * BATCH * PROJ];
__device__ float g_out2[(size_t)(T_STEPS + 1) * BATCH * PROJ];
__device__ float g_c1[BATCH * HID];
__device__ float g_c2[BATCH * HID];
__device__ float g_g1h[BATCH * HID];
__device__ float g_g2h[BATCH * HID];
__device__ int   g_counts[T_STEPS];
__device__ int   g_offsets[T_STEPS + 1];

__device__ volatile unsigned g_genv;   // monotonic across replays
__device__ unsigned g_arrive;          // self-resetting

// ---------------------------------------------------------------------------
// packed f32x2 helpers (proj path)
// ---------------------------------------------------------------------------
__device__ __forceinline__ unsigned long long pk2(float x, float y) {
    unsigned long long d;
    asm("mov.b64 %0, {%1, %2};" : "=l"(d) : "f"(x), "f"(y));
    return d;
}
__device__ __forceinline__ void fma2(unsigned long long& a, unsigned long long b,
                                     unsigned long long c) {
    asm("fma.rn.f32x2 %0, %1, %2, %0;" : "+l"(a) : "l"(b), "l"(c));
}
__device__ __forceinline__ unsigned long long add2(unsigned long long a,
                                                   unsigned long long b) {
    unsigned long long d;
    asm("add.rn.f32x2 %0, %1, %2;" : "=l"(d) : "l"(a), "l"(b));
    return d;
}
__device__ __forceinline__ float2 up2(unsigned long long d) {
    float2 r;
    asm("mov.b64 {%0, %1}, %2;" : "=f"(r.x), "=f"(r.y) : "l"(d));
    return r;
}
__device__ __forceinline__ float sigf(float x) { return 1.f / (1.f + expf(-x)); }

__device__ __forceinline__ uint32_t h2u(float2 f) {
    __half2 h = __float22half2_rn(f);
    return *(uint32_t*)&h;
}

// ---------------------------------------------------------------------------
// fp16 HMMA m16n8k16 (fp32 accumulate)
// ---------------------------------------------------------------------------
__device__ __forceinline__ void mma_f16(float c[4], const uint32_t a[4],
                                        const uint32_t b[2]) {
    asm volatile(
        "mma.sync.aligned.m16n8k16.row.col.f32.f16.f16.f32 "
        "{%0,%1,%2,%3}, {%4,%5,%6,%7}, {%8,%9}, {%0,%1,%2,%3};\n"
        : "+f"(c[0]), "+f"(c[1]), "+f"(c[2]), "+f"(c[3])
        : "r"(a[0]), "r"(a[1]), "r"(a[2]), "r"(a[3]), "r"(b[0]), "r"(b[1]));
}

// ---------------------------------------------------------------------------
// tf32 helpers (3xTF32 split GEMM, Phase A)
// ---------------------------------------------------------------------------
__device__ __forceinline__ uint32_t f2tf(float x) {
    uint32_t r;
    asm("cvt.rna.tf32.f32 %0, %1;" : "=r"(r) : "f"(x));
    return r;
}
__device__ __forceinline__ void mma_tf32(float c[4], const uint32_t a[4],
                                         const uint32_t b[2]) {
    asm volatile(
        "mma.sync.aligned.m16n8k8.row.col.f32.tf32.tf32.f32 "
        "{%0,%1,%2,%3}, {%4,%5,%6,%7}, {%8,%9}, {%0,%1,%2,%3};\n"
        : "+f"(c[0]), "+f"(c[1]), "+f"(c[2]), "+f"(c[3])
        : "r"(a[0]), "r"(a[1]), "r"(a[2]), "r"(a[3]), "r"(b[0]), "r"(b[1]));
}

// ---------------------------------------------------------------------------
// grid-wide barrier
// ---------------------------------------------------------------------------
__device__ __forceinline__ void gsync(unsigned& gen) {
    __syncthreads();
    if (threadIdx.x == 0) {
        unsigned next = gen + 1;
        __threadfence();
        if (atomicAdd(&g_arrive, 1u) == (unsigned)(NBLK - 1)) {
            g_arrive = 0u;
            __threadfence();
            g_genv = next;
        } else {
            while (g_genv != next) {}
            __threadfence();
        }
        gen = next;
    }
    __syncthreads();
}

// ---------------------------------------------------------------------------
// Fused prep: pack gate weights into HMMA fragment order (fp16),
// transpose proj weights (fp32), zero states, packed-seq counts.
// blocks: [0,2048) pb1 | [2048,4096) pb2 | [4096,6144) Wtr1 | [6144,8192) Wtr2
//         8192 counts | (8192,10241) zero
// ---------------------------------------------------------------------------
__global__ void prep_kernel(const float* __restrict__ W_hh1,
                            const float* __restrict__ W_ih2,
                            const float* __restrict__ W_hh2,
                            const float* __restrict__ W_hr1,
                            const float* __restrict__ W_hr2,
                            const int* __restrict__ lens) {
    int bid = blockIdx.x;
    int tid = threadIdx.x;
    if (bid < 2048) {                       // pb1: nt = bid, 32 chunks
        int nt = bid;
        #pragma unroll
        for (int j = 0; j < 4; j++) {
            int i = tid + j * 256;          // 0..1023
            int c = i >> 5, lane = i & 31;
            int gr = lane >> 2, tc = lane & 3;
            int n = nt * 8 + gr;
            int k0 = 16 * c + 2 * tc;
            const float* src = W_hh1 + (size_t)n * 512;
            float2 f0 = *(const float2*)(src + k0);
            float2 f1 = *(const float2*)(src + k0 + 8);
            g_pb1[(size_t)(nt * 32 + c) * 32 + lane] = make_uint2(h2u(f0), h2u(f1));
        }
    } else if (bid < 4096) {                // pb2: nt = bid-2048, 64 chunks
        int nt = bid - 2048;
        #pragma unroll
        for (int j = 0; j < 8; j++) {
            int i = tid + j * 256;          // 0..2047
            int c = i >> 5, lane = i & 31;
            int gr = lane >> 2, tc = lane & 3;
            int n = nt * 8 + gr;
            int k0 = 16 * c + 2 * tc;
            const float* src = (c < 32) ? (W_ih2 + (size_t)n * 1280 + k0)
                                        : (W_hh2 + (size_t)n * 512 + (k0 - 512));
            float2 f0 = *(const float2*)src;
            float2 f1 = *(const float2*)(src + 8);
            g_pb2[(size_t)(nt * 64 + c) * 32 + lane] = make_uint2(h2u(f0), h2u(f1));
        }
    } else if (bid < 8192) {                // proj transposes (32x33 tiles)
        __shared__ float tile[32][33];
        const float* in;
        float* out;
        int tix;
        if (bid < 6144) { in = W_hr1; out = g_Wtr1; tix = bid - 4096; }
        else            { in = W_hr2; out = g_Wtr2; tix = bid - 6144; }
        const int rows = 512, ldin = HID;
        int nbx = rows >> 5;                // 16
        int bx = tix % nbx, by = tix / nbx;
        int j0 = bx * 32, k0 = by * 32;
        int tx = tid & 31, ty = tid >> 5;
        #pragma unroll
        for (int i = 0; i < 32; i += 8) {
            int j = j0 + ty + i, k = k0 + tx;
            tile[ty + i][tx] = in[(size_t)j * ldin + k];
        }
        __syncthreads();
        #pragma unroll
        for (int i = 0; i < 32; i += 8) {
            int k = k0 + ty + i, j = j0 + tx;
            out[(size_t)k * rows + j] = tile[tx][ty + i];
        }
    } else if (bid == 8192) {               // counts
        int t = tid;
        int c = 0;
        #pragma unroll
        for (int b = 0; b < BATCH; b++) c += (lens[b] > t) ? 1 : 0;
        g_counts[t] = c;
        __syncthreads();
        if (t == 0) {
            int s = 0;
            for (int i = 0; i < T_STEPS; i++) { g_offsets[i] = s; s += g_counts[i]; }
            g_offsets[T_STEPS] = s;
        }
    } else {                                // zero
        const size_t n1 = (size_t)(T_STEPS + 1) * BATCH * PROJ;
        const size_t nc = (size_t)BATCH * HID;
        const size_t tot = 2 * n1 + 2 * nc;
        size_t base = (size_t)(bid - 8193) * 256 + tid;
        for (size_t i = base; i < tot; i += (size_t)2048 * 256) {
            if (i < n1)               g_out1[i] = 0.f;
            else if (i < 2 * n1)      g_out2[i - n1] = 0.f;
            else if (i < 2 * n1 + nc) g_c1[i - 2 * n1] = 0.f;
            else                      g_c2[i - 2 * n1 - nc] = 0.f;
        }
    }
}

// ---------------------------------------------------------------------------
// Phase A GEMM on tensor cores: 3xTF32 (fp32-grade accuracy).
// ---------------------------------------------------------------------------
__global__ void __launch_bounds__(256)
sgemm_tf32(const float* __restrict__ A, const float* __restrict__ B,
           const float* __restrict__ bias, float* __restrict__ C,
           int K, int lda, int ldb, int boff) {
    __shared__ float Ah[16 * TSTR], Al[16 * TSTR];
    __shared__ float Bh[16 * TSTR], Bl[16 * TSTR];

    const int tid = threadIdx.x;
    const int m0 = blockIdx.y * 128, n0 = blockIdx.x * 128;
    const int warp = tid >> 5, lane = tid & 31;
    const int wm = (warp >> 2) * 64;
    const int wn = (warp & 3) * 32;
    const int g  = lane >> 2;
    const int tk = lane & 3;

    float c[4][4][4];
    #pragma unroll
    for (int mt = 0; mt < 4; mt++)
        #pragma unroll
        for (int nt = 0; nt < 4; nt++)
            #pragma unroll
            for (int i = 0; i < 4; i++) c[mt][nt][i] = 0.f;

    const int rr = tid >> 4;
    const int cc = tid & 15;

    for (int k0 = 0; k0 < K; k0 += 16) {
        __syncthreads();
        const bool kv = (k0 + cc) < K;
        #pragma unroll
        for (int i = 0; i < 8; i++) {
            int r = rr + i * 16;
            float av = kv ? A[(size_t)(m0 + r) * lda + k0 + cc] : 0.f;
            float bv = kv ? B[(size_t)(n0 + r) * ldb + boff + k0 + cc] : 0.f;
            uint32_t ah = f2tf(av);
            uint32_t bh = f2tf(bv);
            Ah[cc * TSTR + r] = __uint_as_float(ah);
            Al[cc * TSTR + r] = __uint_as_float(f2tf(av - __uint_as_float(ah)));
            Bh[cc * TSTR + r] = __uint_as_float(bh);
            Bl[cc * TSTR + r] = __uint_as_float(f2tf(bv - __uint_as_float(bh)));
        }
        __syncthreads();

        #pragma unroll
        for (int ks = 0; ks < 16; ks += 8) {
            const int kk = ks + tk;
            uint32_t ahf[4][4], alf[4][4], bhf[4][2], blf[4][2];
            #pragma unroll
            for (int mt = 0; mt < 4; mt++) {
                int rb = wm + mt * 16 + g;
                ahf[mt][0] = __float_as_uint(Ah[kk * TSTR + rb]);
                ahf[mt][1] = __float_as_uint(Ah[kk * TSTR + rb + 8]);
                ahf[mt][2] = __float_as_uint(Ah[(kk + 4) * TSTR + rb]);
                ahf[mt][3] = __float_as_uint(Ah[(kk + 4) * TSTR + rb + 8]);
                alf[mt][0] = __float_as_uint(Al[kk * TSTR + rb]);
                alf[mt][1] = __float_as_uint(Al[kk * TSTR + rb + 8]);
                alf[mt][2] = __float_as_uint(Al[(kk + 4) * TSTR + rb]);
                alf[mt][3] = __float_as_uint(Al[(kk + 4) * TSTR + rb + 8]);
            }
            #pragma unroll
            for (int nt = 0; nt < 4; nt++) {
                int nb = wn + nt * 8 + g;
                bhf[nt][0] = __float_as_uint(Bh[kk * TSTR + nb]);
                bhf[nt][1] = __float_as_uint(Bh[(kk + 4) * TSTR + nb]);
                blf[nt][0] = __float_as_uint(Bl[kk * TSTR + nb]);
                blf[nt][1] = __float_as_uint(Bl[(kk + 4) * TSTR + nb]);
            }
            #pragma unroll
            for (int mt = 0; mt < 4; mt++)
                #pragma unroll
                for (int nt = 0; nt < 4; nt++) {
                    mma_tf32(c[mt][nt], ahf[mt], bhf[nt]);
                    mma_tf32(c[mt][nt], ahf[mt], blf[nt]);
                    mma_tf32(c[mt][nt], alf[mt], bhf[nt]);
                }
        }
    }

    #pragma unroll
    for (int nt = 0; nt < 4; nt++) {
        int col = n0 + wn + nt * 8 + 2 * tk;
        float b0 = bias[col], b1 = bias[col + 1];
        #pragma unroll
        for (int mt = 0; mt < 4; mt++) {
            int row0 = m0 + wm + mt * 16 + g;
            float2 v0 = {c[mt][nt][0] + b0, c[mt][nt][1] + b1};
            float2 v1 = {c[mt][nt][2] + b0, c[mt][nt][3] + b1};
            __stcs((float2*)(C + (size_t)row0 * G4H + col), v0);
            __stcs((float2*)(C + (size_t)(row0 + 8) * G4H + col), v1);
        }
    }
}

// ---------------------------------------------------------------------------
// Stage h into A-fragment layout (fp16): af[(c*32+lane)*4 + r] uint32.
// k<512 from src1 (h1), else src2 (h2). NC = number of 16-k chunks.
// ---------------------------------------------------------------------------
template <int NC>
__device__ __forceinline__ void stage_af(const float* __restrict__ src1,
                                         const float* __restrict__ src2,
                                         uint32_t* af) {
    const int tid = threadIdx.x;
    for (int i = tid; i < NC * 32; i += 512) {
        int c = i >> 5, lane = i & 31;
        int gr = lane >> 2, tc = lane & 3;
        int k0 = 16 * c + 2 * tc;
        const float* s = (NC == 32 || k0 < 512) ? (src1 + k0) : (src2 + k0 - 512);
        float2 f0 = *(const float2*)(s + gr * PROJ);
        float2 f1 = *(const float2*)(s + (gr + 8) * PROJ);
        float2 f2 = *(const float2*)(s + gr * PROJ + 8);
        float2 f3 = *(const float2*)(s + (gr + 8) * PROJ + 8);
        *(uint4*)(af + (size_t)i * 4) =
            make_uint4(h2u(f0), h2u(f1), h2u(f2), h2u(f3));
    }
}

// ---------------------------------------------------------------------------
// Gate phase via HMMA: 16 warps, each owns one 8-row N-tile per layer,
// full-K accumulation (no k-split, no reduction). z = acc + xg -> zbuf.
// ---------------------------------------------------------------------------
template <bool DO1, bool DO2>
__device__ __forceinline__ void gate_mma(
    const uint32_t* af, float* zbuf1, float* zbuf2,
    const float* __restrict__ xg1p, const float* __restrict__ xg2p)
{
    const int w = threadIdx.x >> 5, lane = threadIdx.x & 31;
    const int gate = w >> 2, jj8 = (w & 3) << 3;
    const int gr = lane >> 2, tc = lane & 3;
    const int ntg = gate * 512 + blockIdx.x * 4 + (w & 3);

    float acc1[4] = {0.f, 0.f, 0.f, 0.f};
    float acc2[4] = {0.f, 0.f, 0.f, 0.f};

    if (DO1) {
        const uint2* bp = g_pb1 + (size_t)ntg * 32 * 32 + lane;
        #pragma unroll 8
        for (int c = 0; c < 32; c++) {
            uint4 av = *(const uint4*)(af + (size_t)(c * 32 + lane) * 4);
            uint2 bv = bp[(size_t)c * 32];
            uint32_t a[4] = {av.x, av.y, av.z, av.w};
            uint32_t b[2] = {bv.x, bv.y};
            mma_f16(acc1, a, b);
        }
    }
    if (DO2) {
        const uint2* bp = g_pb2 + (size_t)ntg * 64 * 32 + lane;
        #pragma unroll 8
        for (int c = 0; c < 64; c++) {
            uint4 av = *(const uint4*)(af + (size_t)(c * 32 + lane) * 4);
            uint2 bv = bp[(size_t)c * 32];
            uint32_t a[4] = {av.x, av.y, av.z, av.w};
            uint32_t b[2] = {bv.x, bv.y};
            mma_f16(acc2, a, b);
        }
    }

    const int jl = jj8 + 2 * tc;
    const int rowg = gate * HID + blockIdx.x * 32 + jl;
    if (DO1) {
        float2 x0 = __ldcs((const float2*)(xg1p + (size_t)gr * G4H + rowg));
        float2 x1 = __ldcs((const float2*)(xg1p + (size_t)(gr + 8) * G4H + rowg));
        float2 z0 = {acc1[0] + x0.x, acc1[1] + x0.y};
        float2 z1 = {acc1[2] + x1.x, acc1[3] + x1.y};
        *(float2*)&zbuf1[gate * 512 + gr * 32 + jl] = z0;
        *(float2*)&zbuf1[gate * 512 + (gr + 8) * 32 + jl] = z1;
    }
    if (DO2) {
        float2 x0 = __ldcs((const float2*)(xg2p + (size_t)gr * G4H + rowg));
        float2 x1 = __ldcs((const float2*)(xg2p + (size_t)(gr + 8) * G4H + rowg));
        float2 z0 = {acc2[0] + x0.x, acc2[1] + x0.y};
        float2 z1 = {acc2[2] + x1.x, acc2[3] + x1.y};
        *(float2*)&zbuf2[gate * 512 + gr * 32 + jl] = z0;
        *(float2*)&zbuf2[gate * 512 + (gr + 8) * 32 + jl] = z1;
    }
}

// ---------------------------------------------------------------------------
// Cell update for both layers (c-state in registers).
// ---------------------------------------------------------------------------
template <bool DO1, bool DO2>
__device__ __forceinline__ void cell_update(
    const float* zbuf1, const float* zbuf2,
    float& c1r, float& c2r, bool last1, bool last2)
{
    const int tid = threadIdx.x;
    const int b = tid >> 5, jl = tid & 31;
    const size_t off = (size_t)b * HID + blockIdx.x * 32 + jl;
    if (DO1) {
        float zi = zbuf1[0 * 512 + b * 32 + jl];
        float zf = zbuf1[1 * 512 + b * 32 + jl];
        float zg = zbuf1[2 * 512 + b * 32 + jl];
        float zo = zbuf1[3 * 512 + b * 32 + jl];
        float cn = sigf(zf) * c1r + sigf(zi) * tanhf(zg);
        c1r = cn;
        g_g1h[off] = sigf(zo) * tanhf(cn);
        if (last1) g_c1[off] = cn;
    }
    if (DO2) {
        float zi = zbuf2[0 * 512 + b * 32 + jl];
        float zf = zbuf2[1 * 512 + b * 32 + jl];
        float zg = zbuf2[2 * 512 + b * 32 + jl];
        float zo = zbuf2[3 * 512 + b * 32 + jl];
        float cn = sigf(zf) * c2r + sigf(zi) * tanhf(zg);
        c2r = cn;
        g_g2h[off] = sigf(zo) * tanhf(cn);
        if (last2) g_c2[off] = cn;
    }
}

// ---------------------------------------------------------------------------
// Proj staging + main loop + combined reduce (fp32 weights — exact proj).
// ---------------------------------------------------------------------------
__device__ __forceinline__ void stage_g(const float* __restrict__ gh,
                                        int kb, float* gpf) {
    const int tid = threadIdx.x;
    int bb = tid >> 7, k = tid & 127;
    int b0 = 4 * bb;
    float4 v;
    v.x = __ldcs(gh + (size_t)(b0 + 0) * HID + kb + k);
    v.y = __ldcs(gh + (size_t)(b0 + 1) * HID + kb + k);
    v.z = __ldcs(gh + (size_t)(b0 + 2) * HID + kb + k);
    v.w = __ldcs(gh + (size_t)(b0 + 3) * HID + kb + k);
    *(float4*)&gpf[k * HSTR + 4 * bb] = v;
}

__device__ __forceinline__ void proj_loop(
    const float* gpf, const float* __restrict__ Wtr,
    int p0, int kb, unsigned long long* predu)
{
    const int tid = threadIdx.x;
    const int ks = tid >> 7, r = tid & 127;
    const int rowg = r >> 2, bg = (r & 3) << 2;
    const int p4 = p0 + rowg * 4;
    const int kbeg = ks * 32;

    const ulonglong2* wp = (const ulonglong2*)(Wtr + (size_t)(kb + kbeg) * PROJ + p4);
    const float* hp = gpf + kbeg * HSTR + bg;

    unsigned long long acc[2][4];
    #pragma unroll
    for (int i = 0; i < 2; i++)
        #pragma unroll
        for (int j = 0; j < 4; j++) acc[i][j] = 0ull;

    #pragma unroll 8
    for (int k = 0; k < 32; k++) {
        ulonglong2 w = wp[(size_t)k * (PROJ / 4)];
        float4 h = *(const float4*)(hp + k * HSTR);
        unsigned long long h0 = pk2(h.x, h.x), h1 = pk2(h.y, h.y);
        unsigned long long h2 = pk2(h.z, h.z), h3 = pk2(h.w, h.w);
        fma2(acc[0][0], w.x, h0); fma2(acc[1][0], w.y, h0);
        fma2(acc[0][1], w.x, h1); fma2(acc[1][1], w.y, h1);
        fma2(acc[0][2], w.x, h2); fma2(acc[1][2], w.y, h2);
        fma2(acc[0][3], w.x, h3); fma2(acc[1][3], w.y, h3);
    }

    unsigned long long* dst = predu + (size_t)ks * 1152 + r * 9;
    #pragma unroll
    for (int rp = 0; rp < 2; rp++)
        #pragma unroll
        for (int bi = 0; bi < 4; bi++) dst[rp * 4 + bi] = acc[rp][bi];
}

template <bool DO1, bool DO2>
__device__ __forceinline__ void proj_reduce(
    float* __restrict__ hout1, float* __restrict__ hout2,
    const unsigned long long* predu1, const unsigned long long* predu2, int p0)
{
    const int t = threadIdx.x;
    const int layer = t >> 8;
    const int rr = (t >> 1) & 127;
    const int q = t & 1;
    if ((layer == 0 && !DO1) || (layer == 1 && !DO2)) return;

    const unsigned long long* predu = layer ? predu2 : predu1;
    float* hout = layer ? hout2 : hout1;
    const int rowg = rr >> 2, bg = (rr & 3) << 2;
    const int p4 = p0 + rowg * 4;

    #pragma unroll
    for (int bi = 0; bi < 4; bi++) {
        unsigned long long sum = predu[rr * 9 + q * 4 + bi];
        #pragma unroll
        for (int g = 1; g < 4; g++)
            sum = add2(sum, predu[(size_t)g * 1152 + rr * 9 + q * 4 + bi]);
        float2 v = up2(sum);
        float* o = hout + (size_t)(bg + bi) * PROJ + p4 + 2 * q;
        atomicAdd(o + 0, v.x);
        atomicAdd(o + 1, v.y);
    }
}

// ---------------------------------------------------------------------------
// Persistent recurrence: HMMA gates + fp32 proj, fused dual-layer phases.
// ---------------------------------------------------------------------------
__global__ void __launch_bounds__(512, 1) recurrence_kernel() {
    extern __shared__ float smem[];
    uint32_t* af = (uint32_t*)smem;                  // [0, 8192) uint32
    float* zbuf1 = smem + 8192;
    float* zbuf2 = smem + 10240;
    float* gpf1 = smem;
    float* gpf2 = smem + 2560;
    unsigned long long* predu1 = (unsigned long long*)(smem + 5120);
    unsigned long long* predu2 = (unsigned long long*)(smem + 14336);

    const int pt = blockIdx.x & 3;
    const int kc = blockIdx.x >> 2;
    const int p0 = pt * 128, kb = kc * 128;

    unsigned gen = g_genv;
    float c1r = 0.f, c2r = 0.f;

    // ---- prologue: G1(0) ----
    stage_af<32>(g_out1, nullptr, af);
    __syncthreads();
    gate_mma<true, false>(af, zbuf1, zbuf2, g_xg1, nullptr);
    __syncthreads();
    cell_update<true, false>(zbuf1, zbuf2, c1r, c2r, false, false);
    gsync(gen);
    // ---- P1(0) -> out1[1] ----
    stage_g(g_g1h, kb, gpf1);
    __syncthreads();
    proj_loop(gpf1, g_Wtr1, p0, kb, predu1);
    __syncthreads();
    proj_reduce<true, false>(g_out1 + (size_t)1 * (BATCH * PROJ), nullptr,
                             predu1, predu2, p0);
    gsync(gen);

    for (int t = 0; t < T_STEPS - 1; t++) {
        // fused gate phase: G1(t+1) + G2(t)
        stage_af<64>(g_out1 + (size_t)(t + 1) * (BATCH * PROJ),
                     g_out2 + (size_t)t * (BATCH * PROJ), af);
        __syncthreads();
        gate_mma<true, true>(af, zbuf1, zbuf2,
                             g_xg1 + (size_t)(t + 1) * BATCH * G4H,
                             g_xg2 + (size_t)t * BATCH * G4H);
        __syncthreads();
        cell_update<true, true>(zbuf1, zbuf2, c1r, c2r,
                                (t + 1 == T_STEPS - 1), false);
        gsync(gen);
        // fused proj phase: P1(t+1) + P2(t)
        stage_g(g_g1h, kb, gpf1);
        stage_g(g_g2h, kb, gpf2);
        __syncthreads();
        proj_loop(gpf1, g_Wtr1, p0, kb, predu1);
        proj_loop(gpf2, g_Wtr2, p0, kb, predu2);
        __syncthreads();
        proj_reduce<true, true>(g_out1 + (size_t)(t + 2) * (BATCH * PROJ),
                                g_out2 + (size_t)(t + 1) * (BATCH * PROJ),
                                predu1, predu2, p0);
        gsync(gen);
    }

    // ---- tail: G2(255) | P2(255) ----
    {
        int t = T_STEPS - 1;
        stage_af<64>(g_out1 + (size_t)(t + 1) * (BATCH * PROJ),
                     g_out2 + (size_t)t * (BATCH * PROJ), af);
        __syncthreads();
        gate_mma<false, true>(af, zbuf1, zbuf2, nullptr,
                              g_xg2 + (size_t)t * BATCH * G4H);
        __syncthreads();
        cell_update<false, true>(zbuf1, zbuf2, c1r, c2r, false, true);
        gsync(gen);
        stage_g(g_g2h, kb, gpf2);
        __syncthreads();
        proj_loop(gpf2, g_Wtr2, p0, kb, predu2);
        __syncthreads();
        proj_reduce<false, true>(nullptr,
                                 g_out2 + (size_t)(t + 1) * (BATCH * PROJ),
                                 predu1, predu2, p0);
    }
}

// ---------------------------------------------------------------------------
// Heads: one warp per packed token
// ---------------------------------------------------------------------------
__global__ void __launch_bounds__(512) heads_kernel(
    const float* __restrict__ Wp, const float* __restrict__ bp,
    const float* __restrict__ Wa, const float* __restrict__ ba,
    float* __restrict__ out, int total) {
    const int t = blockIdx.x;
    const int w = threadIdx.x >> 5;
    const int lane = threadIdx.x & 31;
    if (w >= g_counts[t]) return;
    const int b = w;
    const int tok = g_offsets[t] + b;

    const float* o1 = g_out1 + (size_t)(t + 1) * (BATCH * PROJ) + (size_t)b * PROJ;
    const float* o2 = g_out2 + (size_t)(t + 1) * (BATCH * PROJ) + (size_t)b * PROJ;
    float v[16];
    #pragma unroll
    for (int i = 0; i < 16; i++) v[i] = o1[lane + 32 * i] + o2[lane + 32 * i];

    __shared__ float sp[16][20];
    __shared__ float sa[16][20];
    #pragma unroll
    for (int o = 0; o < 20; o++) {
        float s1 = 0.f, s2 = 0.f;
        #pragma unroll
        for (int i = 0; i < 16; i++) {
            float x = v[i];
            s1 = fmaf(x, Wp[o * PROJ + lane + 32 * i], s1);
            s2 = fmaf(x, Wa[o * PROJ + lane + 32 * i], s2);
        }
        #pragma unroll
        for (int off = 16; off; off >>= 1) {
            s1 += __shfl_xor_sync(0xffffffffu, s1, off);
            s2 += __shfl_xor_sync(0xffffffffu, s2, off);
        }
        if (lane == 0) { sp[w][o] = s1 + bp[o]; sa[w][o] = s2 + ba[o]; }
    }
    __syncwarp();
    if (lane == 0) {
        float m = -1e30f;
        #pragma unroll
        for (int o = 0; o < 20; o++) m = fmaxf(m, sp[w][o]);
        float e[20], sum = 0.f;
        #pragma unroll
        for (int o = 0; o < 20; o++) { e[o] = expf(sp[w][o] - m); sum += e[o]; }
        float inv = 1.f / sum;
        float* aa = out + (size_t)total * 20;
        #pragma unroll
        for (int o = 0; o < 20; o++) {
            out[(size_t)tok * 20 + o] = e[o] * inv;
            aa[(size_t)tok * 20 + o]  = sa[w][o];
        }
    }
}

// ---------------------------------------------------------------------------
// Final states: h1, c1, h2, c2
// ---------------------------------------------------------------------------
__global__ void finalize_kernel(float* __restrict__ out, int total) {
    const size_t base = (size_t)total * 40;
    const int nH = BATCH * PROJ;
    const int nC = BATCH * HID;
    int idx = blockIdx.x * blockDim.x + threadIdx.x;
    if (idx >= 2 * (nH + nC)) return;
    float v;
    if (idx < nH)                v = g_out1[(size_t)T_STEPS * nH + idx];
    else if (idx < nH + nC)      v = g_c1[idx - nH];
    else if (idx < 2 * nH + nC)  v = g_out2[(size_t)T_STEPS * nH + (idx - nH - nC)];
    else                         v = g_c2[idx - 2 * nH - nC];
    out[base + idx] = v;
}

// ---------------------------------------------------------------------------
// Host launch
// ---------------------------------------------------------------------------
extern "C" void kernel_launch(void* const* d_in, const int* in_sizes, int n_in,
                              void* d_out, int out_size) {
    const float* uncon  = (const float*)d_in[0];
    const float* con    = (const float*)d_in[1];
    const int*   lens   = (const int*)d_in[2];
    const float* W_ih1  = (const float*)d_in[3];
    const float* b1     = (const float*)d_in[4];
    const float* W_hh1  = (const float*)d_in[5];
    const float* W_hr1  = (const float*)d_in[6];
    const float* W_ih2  = (const float*)d_in[7];
    const float* b2     = (const float*)d_in[8];
    const float* W_hh2  = (const float*)d_in[9];
    const float* W_hr2  = (const float*)d_in[10];
    const float* W_pssm = (const float*)d_in[11];
    const float* b_pssm = (const float*)d_in[12];
    const float* W_aa   = (const float*)d_in[13];
    const float* b_aa   = (const float*)d_in[14];
    float* out = (float*)d_out;

    const int total = (out_size - 2 * (BATCH * PROJ + BATCH * HID)) / 40;

    float *p_xg1, *p_xg2;
    cudaGetSymbolAddress((void**)&p_xg1, g_xg1);
    cudaGetSymbolAddress((void**)&p_xg2, g_xg2);

    cudaFuncSetAttribute(recurrence_kernel,
                         cudaFuncAttributeMaxDynamicSharedMemorySize, SM_TOTAL_B);

    // 1: fused prep (HMMA fragment pack + proj transposes + zero + counts)
    prep_kernel<<<10241, 256>>>(W_hh1, W_ih2, W_hh2, W_hr1, W_hr2, lens);
    // 2,3: Phase A on tensor cores (3xTF32)
    sgemm_tf32<<<dim3(G4H / 128, (T_STEPS * BATCH) / 128), 256>>>(
        uncon, W_ih1, b1, p_xg1, F1, F1, F1, 0);
    sgemm_tf32<<<dim3(G4H / 128, (T_STEPS * BATCH) / 128), 256>>>(
        con, W_ih2, b2, p_xg2, F2CON, F2CON, 1280, 512);
    // 4: persistent recurrence (HMMA gates, L2-resident fp16 weights)
    recurrence_kernel<<<NBLK, 512, SM_TOTAL_B>>>();
    // 5,6: heads + final states
    heads_kernel<<<T_STEPS, 512>>>(W_pssm, b_pssm, W_aa, b_aa, out, total);
    finalize_kernel<<<(2 * (BATCH * PROJ + BATCH * HID) + 255) / 256, 256>>>(out, total);
}